// round 13
// baseline (speedup 1.0000x reference)
#include <cuda_runtime.h>
#include <cuda_bf16.h>
#include <cstdint>

#define B_    4
#define KL    128
#define XL    4096
#define DIM   256
#define H_    8
#define HD    32
#define PB    8
#define NDIS  66
#define TDIM  768           // 3*DIM
#define SCALE 0.17677669529663687f
#define NSPLIT 32           // x-splits for k2/k3

// ---------------- scratch (device globals) ----------------
__device__ float    g_QKVx[B_ * XL * TDIM];
__device__ float    g_QKVk[B_ * KL * TDIM];
__device__ unsigned short g_rp[(size_t)B_ * KL * XL];          // rd | polar<<7 (4 MB)
__device__ uint8_t  g_mb[(size_t)B_ * H_ * KL * (XL / 8)];     // transposed mask bits (2 MB)
__device__ float    g_oriP[NSPLIT * B_ * H_ * KL * PB];
__device__ int      g_mo[B_ * H_ * KL];
__device__ float    g_part[(size_t)B_ * H_ * NSPLIT * KL * 33];
__device__ unsigned g_flags;
// pre-split bf16 hi/lo operand storage (u32 = packed bf16x2 along K)
__device__ uint32_t g_xhi[B_ * XL * DIM / 2],  g_xlo[B_ * XL * DIM / 2];
__device__ uint32_t g_khi[B_ * KL * DIM / 2],  g_klo[B_ * KL * DIM / 2];
__device__ uint32_t g_wqh[(DIM / 2) * TDIM],   g_wql[(DIM / 2) * TDIM];
__device__ uint32_t g_wph[(DIM / 2) * DIM],    g_wpl[(DIM / 2) * DIM];
__device__ uint32_t g_pXh[B_ * XL * DIM / 2],  g_pXl[B_ * XL * DIM / 2];
__device__ uint32_t g_pKh[B_ * KL * DIM / 2],  g_pKl[B_ * KL * DIM / 2];

// ---------------- f32x2 packed helpers ----------------
__device__ __forceinline__ uint64_t pk2(float lo, float hi)
{
    uint64_t r;
    asm("mov.b64 %0, {%1, %2};" : "=l"(r) : "f"(lo), "f"(hi));
    return r;
}
__device__ __forceinline__ void upk2(float& lo, float& hi, uint64_t v)
{
    asm("mov.b64 {%0, %1}, %2;" : "=f"(lo), "=f"(hi) : "l"(v));
}
__device__ __forceinline__ void fma2(uint64_t& d, uint64_t a, uint64_t b)
{
    asm("fma.rn.f32x2 %0, %1, %2, %0;" : "+l"(d) : "l"(a), "l"(b));
}

// ---------------- bf16 split helper ----------------
__device__ __forceinline__ uint32_t split_pack(float x0, float x1, uint32_t& lo_pack)
{
    __nv_bfloat16 h0 = __float2bfloat16(x0);
    __nv_bfloat16 h1 = __float2bfloat16(x1);
    float l0 = x0 - __bfloat162float(h0);
    float l1 = x1 - __bfloat162float(h1);
    __nv_bfloat162 hp = __halves2bfloat162(h0, h1);
    __nv_bfloat162 lp = __halves2bfloat162(__float2bfloat16(l0), __float2bfloat16(l1));
    lo_pack = *(uint32_t*)&lp;
    return *(uint32_t*)&hp;
}

// ---------------- mask dtype probe ----------------
__global__ void det_reset() { if (threadIdx.x == 0) g_flags = 0u; }

__global__ void det_scan(const unsigned* __restrict__ w)
{
    int i = blockIdx.x * blockDim.x + threadIdx.x;
    unsigned v = w[i];
    unsigned f = 0;
    if (v == 0x3F800000u) f |= 1u;
    else if (v != 0u && v != 1u) f |= 2u;
    for (int o = 16; o > 0; o >>= 1) f |= __shfl_xor_sync(0xffffffffu, f, o);
    if ((threadIdx.x & 31) == 0 && f) atomicOr(&g_flags, f);
}

// ---------------- rp16: rd|polar<<7 -> u16 (b,k,x); h-independent ---------
__global__ void rp16(const int* __restrict__ rd, const int* __restrict__ polar)
{
    int i = blockIdx.x * blockDim.x + threadIdx.x;      // u32-pair index
    if (i >= B_ * KL * XL / 2) return;
    int2 r = *(const int2*)&rd[2 * i];
    int2 p = *(const int2*)&polar[2 * i];
    unsigned lo = (unsigned)(r.x | (p.x << 7));
    unsigned hi = (unsigned)(r.y | (p.y << 7));
    ((unsigned*)g_rp)[i] = lo | (hi << 16);
}

// ---------------- maskbit: transpose + bit-pack mask -> g_mb --------------
// grid (XL/64, KL/32, B_), block (32,8); loops h
__global__ void maskbit(const void* __restrict__ mask)
{
    __shared__ uint8_t m_sh[64][36];   // [x][k]
    unsigned flags = g_flags;
    int mode = (flags & 1u) ? 2 : ((flags & 2u) ? 0 : 1);  // 0=u8 1=i32 2=f32
    int x0 = blockIdx.x * 64, k0 = blockIdx.y * 32, b = blockIdx.z;
    int tx = threadIdx.x, ty = threadIdx.y;
    int tid = ty * 32 + tx;
    int ki = tid >> 3, jb = tid & 7;   // output: row k0+ki, byte jb (8 x-bits)

    for (int h = 0; h < H_; h++) {
        size_t mb = ((size_t)((b * H_ + h)) * XL + x0) * KL + k0;
#pragma unroll
        for (int xi = ty; xi < 64; xi += 8) {
            uint8_t v;
            if (mode == 1)      v = ((const int*)mask)[mb + (size_t)xi * KL + tx] != 0;
            else if (mode == 2) v = ((const float*)mask)[mb + (size_t)xi * KL + tx] != 0.f;
            else                v = ((const uint8_t*)mask)[mb + (size_t)xi * KL + tx] != 0;
            m_sh[xi][tx] = v;
        }
        __syncthreads();
        uint8_t byte = 0;
#pragma unroll
        for (int i = 0; i < 8; i++)
            byte |= (uint8_t)(m_sh[8 * jb + i][ki] << i);
        g_mb[((size_t)((b * H_ + h) * KL + k0 + ki)) * (XL / 8) + (x0 >> 3) + jb] = byte;
        __syncthreads();
    }
}

// ---------------- presplit kernels ----------------
__global__ void presplitA(const float* __restrict__ A,
                          uint32_t* __restrict__ hi, uint32_t* __restrict__ lo, int n)
{
    int i = blockIdx.x * blockDim.x + threadIdx.x;
    if (i >= n) return;
    float2 v = *(const float2*)&A[2 * i];
    uint32_t l, h = split_pack(v.x, v.y, l);
    hi[i] = h; lo[i] = l;
}

__global__ void presplitB(const float* __restrict__ Bm,
                          uint32_t* __restrict__ hi, uint32_t* __restrict__ lo, int N, int n)
{
    int i = blockIdx.x * blockDim.x + threadIdx.x;
    if (i >= n) return;
    int p = i / N, c = i - p * N;
    uint32_t l, h = split_pack(Bm[(size_t)(2 * p) * N + c], Bm[(size_t)(2 * p + 1) * N + c], l);
    hi[i] = h; lo[i] = l;
}

// ---------------- bf16x3 GEMM (R11 best config) ----------------
__device__ __forceinline__ void mma_bf16(float* c, const uint32_t* a, uint32_t b0, uint32_t b1)
{
    asm("mma.sync.aligned.m16n8k16.row.col.f32.bf16.bf16.f32 "
        "{%0,%1,%2,%3}, {%4,%5,%6,%7}, {%8,%9}, {%0,%1,%2,%3};"
        : "+f"(c[0]), "+f"(c[1]), "+f"(c[2]), "+f"(c[3])
        : "r"(a[0]), "r"(a[1]), "r"(a[2]), "r"(a[3]), "r"(b0), "r"(b1));
}

__global__ __launch_bounds__(256, 2) void gemm_pre(
    const uint32_t* __restrict__ Ahi, const uint32_t* __restrict__ Alo,
    const uint32_t* __restrict__ Bhi, const uint32_t* __restrict__ Blo,
    const float* __restrict__ bias, float* __restrict__ C,
    int M, int N, int K)
{
    __shared__ uint32_t AsH[128][20];
    __shared__ uint32_t AsL[128][20];
    __shared__ uint32_t BsH[16][136];
    __shared__ uint32_t BsL[16][136];
    int tid = threadIdx.x;
    int wid = tid >> 5, lane = tid & 31;
    int g = lane >> 2, t = lane & 3;
    int wm = wid & 1, wn = wid >> 1;
    int cCol = blockIdx.x, cRow = blockIdx.y;
    const int KP = K >> 1;

    float acc[4][4][4];
#pragma unroll
    for (int i = 0; i < 4; i++)
#pragma unroll
        for (int j = 0; j < 4; j++)
#pragma unroll
            for (int c = 0; c < 4; c++) acc[i][j][c] = 0.f;

    for (int k0p = 0; k0p < KP; k0p += 16) {
#pragma unroll
        for (int j = 0; j < 4; j++) {
            int f = tid + 256 * j;
            int r = f >> 3, p2 = (f & 7) * 2;
            size_t off = (size_t)(cRow * 128 + r) * KP + k0p + p2;
            uint2 h = *(const uint2*)&Ahi[off];
            uint2 l = *(const uint2*)&Alo[off];
            AsH[r][p2] = h.x; AsH[r][p2 + 1] = h.y;
            AsL[r][p2] = l.x; AsL[r][p2 + 1] = l.y;
        }
#pragma unroll
        for (int j = 0; j < 4; j++) {
            int f = tid + 256 * j;
            int pr = f >> 6, c2 = (f & 63) * 2;
            size_t off = (size_t)(k0p + pr) * N + cCol * 128 + c2;
            uint2 h = *(const uint2*)&Bhi[off];
            uint2 l = *(const uint2*)&Blo[off];
            BsH[pr][c2] = h.x; BsH[pr][c2 + 1] = h.y;
            BsL[pr][c2] = l.x; BsL[pr][c2 + 1] = l.y;
        }
        __syncthreads();

#pragma unroll
        for (int kk = 0; kk < 2; kk++) {
            uint32_t ah[4][4], al[4][4];
#pragma unroll
            for (int mi = 0; mi < 4; mi++) {
                int ar = wm * 64 + mi * 16 + g;
                int pc = kk * 8 + t;
                ah[mi][0] = AsH[ar][pc];         al[mi][0] = AsL[ar][pc];
                ah[mi][1] = AsH[ar + 8][pc];     al[mi][1] = AsL[ar + 8][pc];
                ah[mi][2] = AsH[ar][pc + 4];     al[mi][2] = AsL[ar][pc + 4];
                ah[mi][3] = AsH[ar + 8][pc + 4]; al[mi][3] = AsL[ar + 8][pc + 4];
            }
#pragma unroll
            for (int ni = 0; ni < 4; ni++) {
                int bc = wn * 32 + ni * 8 + g;
                int pr = kk * 8 + t;
                uint32_t bh0 = BsH[pr][bc], bh1 = BsH[pr + 4][bc];
                uint32_t bl0 = BsL[pr][bc], bl1 = BsL[pr + 4][bc];
#pragma unroll
                for (int mi = 0; mi < 4; mi++) {
                    mma_bf16(acc[mi][ni], ah[mi], bh0, bh1);
                    mma_bf16(acc[mi][ni], al[mi], bh0, bh1);
                    mma_bf16(acc[mi][ni], ah[mi], bl0, bl1);
                }
            }
        }
        __syncthreads();
    }

#pragma unroll
    for (int mi = 0; mi < 4; mi++) {
#pragma unroll
        for (int ni = 0; ni < 4; ni++) {
            int r0 = cRow * 128 + wm * 64 + mi * 16 + g;
            int c0 = cCol * 128 + wn * 32 + ni * 8 + 2 * t;
            float b0 = bias ? bias[c0] : 0.f;
            float b1 = bias ? bias[c0 + 1] : 0.f;
            float2 v01 = make_float2(acc[mi][ni][0] + b0, acc[mi][ni][1] + b1);
            float2 v23 = make_float2(acc[mi][ni][2] + b0, acc[mi][ni][3] + b1);
            *(float2*)&C[(size_t)r0 * N + c0] = v01;
            *(float2*)&C[(size_t)(r0 + 8) * N + c0] = v23;
        }
    }
}

// ---------------- K2: orientation bins (rp-based) ----------------
__global__ __launch_bounds__(128) void k2_scores()
{
    int k = threadIdx.x;
    int xc = blockIdx.x, h = blockIdx.y, b = blockIdx.z;
    int bh = b * H_ + h;
    int xbase = xc * (XL / NSPLIT);
    __shared__ float kx_sh[64 * 32];
    __shared__ unsigned pk_sh[128 * 33];

    uint64_t kq2[16];
    {
        const uint64_t* kqp = (const uint64_t*)&g_QKVk[((size_t)(b * KL + k)) * TDIM + h * HD];
#pragma unroll
        for (int i = 0; i < 16; i++) kq2[i] = kqp[i];
    }

    float bins[8];
#pragma unroll
    for (int o = 0; o < 8; o++) bins[o] = 0.f;

    const unsigned* pkg = (const unsigned*)&g_rp[(size_t)b * KL * XL];

    for (int c = 0; c < 2; c++) {
        int xs = xbase + c * 64;
        __syncthreads();
        for (int g = threadIdx.x; g < 512; g += 128) {
            int row = g >> 3, c4 = g & 7;
            ((float4*)kx_sh)[g] =
                *(const float4*)&g_QKVx[((size_t)(b * XL + xs + row)) * TDIM + DIM + h * HD + c4 * 4];
        }
        for (int g = threadIdx.x; g < 128 * 32; g += 128) {
            int row = g >> 5, col = g & 31;
            pk_sh[row * 33 + col] = pkg[(size_t)row * (XL / 2) + (xs >> 1) + col];
        }
        __syncthreads();
        const unsigned short* prow = (const unsigned short*)&pk_sh[k * 33];
        for (int j0 = 0; j0 < 64; j0 += 4) {
#pragma unroll
            for (int jj = 0; jj < 4; jj++) {
                const ulonglong2* kx2 = (const ulonglong2*)&kx_sh[(j0 + jj) * 32];
                uint64_t sa = 0;
#pragma unroll
                for (int d = 0; d < 8; d++) {
                    ulonglong2 v = kx2[d];
                    fma2(sa, kq2[2 * d], v.x);
                    fma2(sa, kq2[2 * d + 1], v.y);
                }
                float s0, s1;
                upk2(s0, s1, sa);
                float as = fabsf((s0 + s1) * SCALE);
                int pv = (prow[j0 + jj] >> 7) & 7;
#pragma unroll
                for (int o = 0; o < 8; o++) bins[o] += (pv == o) ? as : 0.f;
            }
        }
    }
    float* orow = &g_oriP[((size_t)xc * B_ * H_ * KL + bh * KL + k) * 8];
#pragma unroll
    for (int o = 0; o < 8; o++) orow[o] = bins[o];
}

// ---------------- K2c: reduce slices + argmax ----------------
__global__ void k2_argmax()
{
    int idx = blockIdx.x * blockDim.x + threadIdx.x;
    if (idx >= B_ * H_ * KL) return;
    float s[8];
#pragma unroll
    for (int o = 0; o < 8; o++) s[o] = 0.f;
    for (int xc = 0; xc < NSPLIT; xc++) {
        const float* p = &g_oriP[((size_t)xc * B_ * H_ * KL + idx) * 8];
#pragma unroll
        for (int o = 0; o < 8; o++) s[o] += p[o];
    }
    int best = 0;
    float bv = s[0];
#pragma unroll
    for (int p = 1; p < 8; p++)
        if (s[p] > bv) { bv = s[p]; best = p; }
    g_mo[idx] = best;
}

// ---------------- K3: kernel->x attention (rp + mask bits) ----------------
__global__ __launch_bounds__(128) void k3_kattn(
    const float* __restrict__ dis_embed, const float* __restrict__ polar_emb)
{
    int k = threadIdx.x;
    int xs = blockIdx.x, h = blockIdx.y, b = blockIdx.z;
    int bh = b * H_ + h;
    __shared__ float kx_sh[64 * 32];
    __shared__ float V_sh[64 * 32];
    __shared__ unsigned pk_sh[128 * 33];
    __shared__ float de_sh[NDIS];
    __shared__ float pe_sh[8];
    if (k < NDIS) de_sh[k] = dis_embed[k * H_ + h];
    if (k < 8) pe_sh[k] = polar_emb[k];
    int mo = g_mo[bh * KL + k];

    uint64_t kq2[16];
    {
        const uint64_t* kqp = (const uint64_t*)&g_QKVk[((size_t)(b * KL + k)) * TDIM + h * HD];
#pragma unroll
        for (int i = 0; i < 16; i++) kq2[i] = kqp[i];
    }

    const unsigned* pkg = (const unsigned*)&g_rp[(size_t)b * KL * XL];
    const uint8_t* mrow = &g_mb[((size_t)bh * KL + k) * (XL / 8)];

    float l = 0.f;
    uint64_t acc2[16];
#pragma unroll
    for (int d = 0; d < 16; d++) acc2[d] = 0;

    int xbase = xs * (XL / NSPLIT);
    for (int c = 0; c < 2; c++) {
        int x0 = xbase + c * 64;
        uint64_t mbits = *(const uint64_t*)&mrow[x0 >> 3];
        __syncthreads();
        for (int g = threadIdx.x; g < 512; g += 128) {
            int row = g >> 3, c4 = g & 7;
            size_t rb = ((size_t)(b * XL + x0 + row)) * TDIM + h * HD + c4 * 4;
            ((float4*)kx_sh)[g] = *(const float4*)&g_QKVx[rb + DIM];
            ((float4*)V_sh)[g]  = *(const float4*)&g_QKVx[rb + 2 * DIM];
        }
        for (int g = threadIdx.x; g < 128 * 32; g += 128) {
            int row = g >> 5, col = g & 31;
            pk_sh[row * 33 + col] = pkg[(size_t)row * (XL / 2) + (x0 >> 1) + col];
        }
        __syncthreads();
        const unsigned short* prow = (const unsigned short*)&pk_sh[k * 33];
        for (int j0 = 0; j0 < 64; j0 += 4) {
#pragma unroll
            for (int jj = 0; jj < 4; jj++) {
                int j = j0 + jj;
                const ulonglong2* kx2 = (const ulonglong2*)&kx_sh[j * 32];
                uint64_t sa = 0;
#pragma unroll
                for (int d = 0; d < 8; d++) {
                    ulonglong2 v = kx2[d];
                    fma2(sa, kq2[2 * d], v.x);
                    fma2(sa, kq2[2 * d + 1], v.y);
                }
                float s0, s1;
                upk2(s0, s1, sa);
                unsigned short p = prow[j];
                float t = (s0 + s1) * SCALE + de_sh[p & 127] + pe_sh[(((p >> 7) & 7) - mo) & 7];
                float w = ((mbits >> j) & 1) ? 0.f : __expf(t);
                l += w;
                uint64_t wpk = pk2(w, w);
                const ulonglong2* vp = (const ulonglong2*)&V_sh[j * 32];
#pragma unroll
                for (int d = 0; d < 8; d++) {
                    ulonglong2 v = vp[d];
                    fma2(acc2[2 * d], wpk, v.x);
                    fma2(acc2[2 * d + 1], wpk, v.y);
                }
            }
        }
    }
    float* pp = &g_part[(((size_t)bh * NSPLIT + xs) * KL + k) * 33];
    pp[0] = l;
#pragma unroll
    for (int d = 0; d < 16; d++) {
        float a0, a1;
        upk2(a0, a1, acc2[d]);
        pp[1 + 2 * d] = a0;
        pp[2 + 2 * d] = a1;
    }
}

// ---------------- K3c: combine x-splits -> preK (bf16 hi/lo out) ----------
__global__ void k3_combine()
{
    int idx = blockIdx.x * blockDim.x + threadIdx.x;
    if (idx >= B_ * H_ * KL * 16) return;
    int d2 = idx & 15;
    int k = (idx >> 4) & (KL - 1);
    int bh = idx >> 11;
    int h = bh % H_, b = bh / H_;
    const float* base = &g_part[((size_t)bh * NSPLIT) * KL * 33 + (size_t)k * 33];
    float L = 0.f, A0 = 0.f, A1 = 0.f;
    const size_t SSTR = (size_t)KL * 33;
#pragma unroll 8
    for (int s = 0; s < NSPLIT; s++) {
        L  += base[s * SSTR];
        A0 += base[s * SSTR + 1 + 2 * d2];
        A1 += base[s * SSTR + 2 + 2 * d2];
    }
    float invL = 1.f / L;
    uint32_t lo, hi = split_pack(A0 * invL, A1 * invL, lo);
    size_t o = ((size_t)b * KL + k) * (DIM / 2) + h * (HD / 2) + d2;
    g_pKh[o] = hi;
    g_pKl[o] = lo;
}

// ---------------- K4: x->kernel attention (rp + mask-bit tile) ------------
__global__ __launch_bounds__(128) void k4_xattn(
    const float* __restrict__ dis_embed, const float* __restrict__ polar_emb)
{
    __shared__ float kk_sh[KL * HD];
    __shared__ float kv_sh[KL * HD];
    __shared__ uint32_t mb_sh[KL][4];    // mask bits for this 128-x block
    __shared__ float de_sh[NDIS];
    __shared__ float pe_sh[8];
    __shared__ int   mo_sh[KL];
    int tid = threadIdx.x;
    int xc = blockIdx.x, h = blockIdx.y, b = blockIdx.z;
    int bh = b * H_ + h;

    for (int g = tid; g < KL * HD / 4; g += 128) {
        int row = g >> 3, c4 = g & 7;
        ((float4*)kk_sh)[g] =
            *(const float4*)&g_QKVk[((size_t)(b * KL + row)) * TDIM + DIM + h * HD + c4 * 4];
        ((float4*)kv_sh)[g] =
            *(const float4*)&g_QKVk[((size_t)(b * KL + row)) * TDIM + 2 * DIM + h * HD + c4 * 4];
    }
    // one LDG.128 per thread: mask bits row tid, 16 bytes covering x block
    *(uint4*)&mb_sh[tid][0] =
        *(const uint4*)&g_mb[((size_t)bh * KL + tid) * (XL / 8) + xc * 16];
    if (tid < NDIS) de_sh[tid] = dis_embed[tid * H_ + h];
    if (tid < 8) pe_sh[tid] = polar_emb[tid];
    if (tid < KL) mo_sh[tid] = g_mo[bh * KL + tid];
    __syncthreads();

    int x = xc * 128 + tid;
    int wsel = tid >> 5, bsel = tid & 31;
    uint64_t q2[16];
    {
        const uint64_t* qp = (const uint64_t*)&g_QKVx[((size_t)(b * XL + x)) * TDIM + h * HD];
#pragma unroll
        for (int i = 0; i < 16; i++) q2[i] = qp[i];
    }
    const unsigned short* rp = &g_rp[(size_t)b * KL * XL + x];

    float l = 0.f;
    uint64_t acc2[16];
#pragma unroll
    for (int d = 0; d < 16; d++) acc2[d] = 0;

    for (int k0 = 0; k0 < KL; k0 += 4) {
#pragma unroll
        for (int ki = 0; ki < 4; ki++) {
            int kidx = k0 + ki;
            const ulonglong2* kkp = (const ulonglong2*)&kk_sh[kidx * HD];
            uint64_t sa = 0;
#pragma unroll
            for (int d = 0; d < 8; d++) {
                ulonglong2 v = kkp[d];
                fma2(sa, q2[2 * d], v.x);
                fma2(sa, q2[2 * d + 1], v.y);
            }
            float s0, s1;
            upk2(s0, s1, sa);
            unsigned short p = rp[(size_t)kidx * XL];
            float t = (s0 + s1) * SCALE + de_sh[p & 127] + pe_sh[(((p >> 7) & 7) - mo_sh[kidx]) & 7];
            float w = ((mb_sh[kidx][wsel] >> bsel) & 1u) ? 0.f : __expf(t);
            l += w;
            uint64_t wpk = pk2(w, w);
            const ulonglong2* vp = (const ulonglong2*)&kv_sh[kidx * HD];
#pragma unroll
            for (int d = 0; d < 8; d++) {
                ulonglong2 v = vp[d];
                fma2(acc2[2 * d], wpk, v.x);
                fma2(acc2[2 * d + 1], wpk, v.y);
            }
        }
    }
    float invl = 1.f / l;
    size_t ob = ((size_t)(b * XL + x)) * (DIM / 2) + h * (HD / 2);
#pragma unroll
    for (int d2 = 0; d2 < 16; d2++) {
        float a0, a1;
        upk2(a0, a1, acc2[d2]);
        uint32_t lo, hi = split_pack(a0 * invl, a1 * invl, lo);
        g_pXh[ob + d2] = hi;
        g_pXl[ob + d2] = lo;
    }
}

// ---------------- host launcher ----------------
extern "C" void kernel_launch(void* const* d_in, const int* in_sizes, int n_in,
                              void* d_out, int out_size)
{
    const float* x     = (const float*)d_in[0];
    const float* kern  = (const float*)d_in[1];
    const int*   rd    = (const int*)d_in[2];
    const int*   polar = (const int*)d_in[3];
    const void*  mask  = d_in[4];
    const float* Wqkv  = (const float*)d_in[5];
    const float* dis   = (const float*)d_in[6];
    const float* pemb  = (const float*)d_in[7];
    const float* Wproj = (const float*)d_in[8];
    const float* bproj = (const float*)d_in[9];
    float* out = (float*)d_out;

    float* pQKVx; cudaGetSymbolAddress((void**)&pQKVx, g_QKVx);
    float* pQKVk; cudaGetSymbolAddress((void**)&pQKVk, g_QKVk);
    uint32_t *pxh, *pxl, *pkh, *pkl, *pwqh, *pwql, *pwph, *pwpl, *pXh, *pXl, *pKh, *pKl;
    cudaGetSymbolAddress((void**)&pxh, g_xhi);  cudaGetSymbolAddress((void**)&pxl, g_xlo);
    cudaGetSymbolAddress((void**)&pkh, g_khi);  cudaGetSymbolAddress((void**)&pkl, g_klo);
    cudaGetSymbolAddress((void**)&pwqh, g_wqh); cudaGetSymbolAddress((void**)&pwql, g_wql);
    cudaGetSymbolAddress((void**)&pwph, g_wph); cudaGetSymbolAddress((void**)&pwpl, g_wpl);
    cudaGetSymbolAddress((void**)&pXh, g_pXh);  cudaGetSymbolAddress((void**)&pXl, g_pXl);
    cudaGetSymbolAddress((void**)&pKh, g_pKh);  cudaGetSymbolAddress((void**)&pKl, g_pKl);

    // mask dtype probe + compact bias/mask tables
    det_reset<<<1, 32>>>();
    det_scan<<<256, 256>>>((const unsigned*)mask);
    rp16<<<(B_ * KL * XL / 2 + 255) / 256, 256>>>(rd, polar);
    maskbit<<<dim3(XL / 64, KL / 32, B_), dim3(32, 8)>>>(mask);

    // pre-split GEMM operands
    presplitA<<<(B_ * XL * DIM / 2 + 255) / 256, 256>>>(x, pxh, pxl, B_ * XL * DIM / 2);
    presplitA<<<(B_ * KL * DIM / 2 + 255) / 256, 256>>>(kern, pkh, pkl, B_ * KL * DIM / 2);
    presplitB<<<((DIM / 2) * TDIM + 255) / 256, 256>>>(Wqkv, pwqh, pwql, TDIM, (DIM / 2) * TDIM);
    presplitB<<<((DIM / 2) * DIM + 255) / 256, 256>>>(Wproj, pwph, pwpl, DIM, (DIM / 2) * DIM);

    // QKV projections
    gemm_pre<<<dim3(TDIM / 128, (B_ * XL) / 128), 256>>>(pxh, pxl, pwqh, pwql, nullptr, pQKVx, B_ * XL, TDIM, DIM);
    gemm_pre<<<dim3(TDIM / 128, (B_ * KL) / 128), 256>>>(pkh, pkl, pwqh, pwql, nullptr, pQKVk, B_ * KL, TDIM, DIM);

    // orientation bins + argmax
    k2_scores<<<dim3(NSPLIT, H_, B_), 128>>>();
    k2_argmax<<<(B_ * H_ * KL + 255) / 256, 256>>>();

    // kernel->x attention
    k3_kattn<<<dim3(NSPLIT, H_, B_), 128>>>(dis, pemb);
    k3_combine<<<(B_ * H_ * KL * 16 + 255) / 256, 256>>>();

    // x->kernel attention
    k4_xattn<<<dim3(XL / 128, H_, B_), 128>>>(dis, pemb);

    // output projections
    gemm_pre<<<dim3(DIM / 128, (B_ * XL) / 128), 256>>>(pXh, pXl, pwph, pwpl, bproj, out, B_ * XL, DIM, DIM);
    gemm_pre<<<dim3(DIM / 128, (B_ * KL) / 128), 256>>>(pKh, pKl, pwph, pwpl, bproj, out + (size_t)B_ * XL * DIM, B_ * KL, DIM, DIM);
}

// round 14
// speedup vs baseline: 1.0601x; 1.0601x over previous
#include <cuda_runtime.h>
#include <cuda_bf16.h>
#include <cstdint>

#define B_    4
#define KL    128
#define XL    4096
#define DIM   256
#define H_    8
#define HD    32
#define PB    8
#define NDIS  66
#define TDIM  768           // 3*DIM
#define SCALE 0.17677669529663687f
#define NSPLIT 32           // x-splits for k2/k3

// ---------------- scratch (device globals) ----------------
__device__ float    g_QKVx[B_ * XL * TDIM];
__device__ float    g_QKVk[B_ * KL * TDIM];
__device__ unsigned short g_rp[(size_t)B_ * KL * XL];          // rd | polar<<7 (4 MB)
__device__ uint8_t  g_mb[(size_t)B_ * H_ * KL * (XL / 8)];     // transposed mask bits (2 MB)
__device__ float    g_oriP[NSPLIT * B_ * H_ * KL * PB];
__device__ int      g_mo[B_ * H_ * KL];
__device__ float    g_part[(size_t)B_ * H_ * NSPLIT * KL * 33];
__device__ unsigned g_flags;
// pre-split bf16 hi/lo operand storage (u32 = packed bf16x2 along K)
__device__ uint32_t g_xhi[B_ * XL * DIM / 2],  g_xlo[B_ * XL * DIM / 2];
__device__ uint32_t g_khi[B_ * KL * DIM / 2],  g_klo[B_ * KL * DIM / 2];
__device__ uint32_t g_wqh[(DIM / 2) * TDIM],   g_wql[(DIM / 2) * TDIM];
__device__ uint32_t g_wph[(DIM / 2) * DIM],    g_wpl[(DIM / 2) * DIM];
__device__ uint32_t g_pXh[B_ * XL * DIM / 2],  g_pXl[B_ * XL * DIM / 2];
__device__ uint32_t g_pKh[B_ * KL * DIM / 2],  g_pKl[B_ * KL * DIM / 2];

// ---------------- f32x2 packed helpers ----------------
__device__ __forceinline__ uint64_t pk2(float lo, float hi)
{
    uint64_t r;
    asm("mov.b64 %0, {%1, %2};" : "=l"(r) : "f"(lo), "f"(hi));
    return r;
}
__device__ __forceinline__ void upk2(float& lo, float& hi, uint64_t v)
{
    asm("mov.b64 {%0, %1}, %2;" : "=f"(lo), "=f"(hi) : "l"(v));
}
__device__ __forceinline__ void fma2(uint64_t& d, uint64_t a, uint64_t b)
{
    asm("fma.rn.f32x2 %0, %1, %2, %0;" : "+l"(d) : "l"(a), "l"(b));
}

// ---------------- bf16 split helper ----------------
__device__ __forceinline__ uint32_t split_pack(float x0, float x1, uint32_t& lo_pack)
{
    __nv_bfloat16 h0 = __float2bfloat16(x0);
    __nv_bfloat16 h1 = __float2bfloat16(x1);
    float l0 = x0 - __bfloat162float(h0);
    float l1 = x1 - __bfloat162float(h1);
    __nv_bfloat162 hp = __halves2bfloat162(h0, h1);
    __nv_bfloat162 lp = __halves2bfloat162(__float2bfloat16(l0), __float2bfloat16(l1));
    lo_pack = *(uint32_t*)&lp;
    return *(uint32_t*)&hp;
}

// ---------------- mask dtype probe ----------------
__global__ void det_reset() { if (threadIdx.x == 0) g_flags = 0u; }

__global__ void det_scan(const unsigned* __restrict__ w)
{
    int i = blockIdx.x * blockDim.x + threadIdx.x;
    unsigned v = w[i];
    unsigned f = 0;
    if (v == 0x3F800000u) f |= 1u;
    else if (v != 0u && v != 1u) f |= 2u;
    for (int o = 16; o > 0; o >>= 1) f |= __shfl_xor_sync(0xffffffffu, f, o);
    if ((threadIdx.x & 31) == 0 && f) atomicOr(&g_flags, f);
}

// ---------------- rp16: rd|polar<<7 -> u16 (b,k,x) ----------------
__global__ void rp16(const int* __restrict__ rd, const int* __restrict__ polar)
{
    int i = blockIdx.x * blockDim.x + threadIdx.x;
    if (i >= B_ * KL * XL / 2) return;
    int2 r = *(const int2*)&rd[2 * i];
    int2 p = *(const int2*)&polar[2 * i];
    unsigned lo = (unsigned)(r.x | (p.x << 7));
    unsigned hi = (unsigned)(r.y | (p.y << 7));
    ((unsigned*)g_rp)[i] = lo | (hi << 16);
}

// ---------------- maskbit: transpose + bit-pack mask -> g_mb --------------
__global__ void maskbit(const void* __restrict__ mask)
{
    __shared__ uint8_t m_sh[64][36];
    unsigned flags = g_flags;
    int mode = (flags & 1u) ? 2 : ((flags & 2u) ? 0 : 1);
    int x0 = blockIdx.x * 64, k0 = blockIdx.y * 32, b = blockIdx.z;
    int tx = threadIdx.x, ty = threadIdx.y;
    int tid = ty * 32 + tx;
    int ki = tid >> 3, jb = tid & 7;

    for (int h = 0; h < H_; h++) {
        size_t mb = ((size_t)((b * H_ + h)) * XL + x0) * KL + k0;
#pragma unroll
        for (int xi = ty; xi < 64; xi += 8) {
            uint8_t v;
            if (mode == 1)      v = ((const int*)mask)[mb + (size_t)xi * KL + tx] != 0;
            else if (mode == 2) v = ((const float*)mask)[mb + (size_t)xi * KL + tx] != 0.f;
            else                v = ((const uint8_t*)mask)[mb + (size_t)xi * KL + tx] != 0;
            m_sh[xi][tx] = v;
        }
        __syncthreads();
        uint8_t byte = 0;
#pragma unroll
        for (int i = 0; i < 8; i++)
            byte |= (uint8_t)(m_sh[8 * jb + i][ki] << i);
        g_mb[((size_t)((b * H_ + h) * KL + k0 + ki)) * (XL / 8) + (x0 >> 3) + jb] = byte;
        __syncthreads();
    }
}

// ---------------- presplit kernels ----------------
__global__ void presplitA(const float* __restrict__ A,
                          uint32_t* __restrict__ hi, uint32_t* __restrict__ lo, int n)
{
    int i = blockIdx.x * blockDim.x + threadIdx.x;
    if (i >= n) return;
    float2 v = *(const float2*)&A[2 * i];
    uint32_t l, h = split_pack(v.x, v.y, l);
    hi[i] = h; lo[i] = l;
}

__global__ void presplitB(const float* __restrict__ Bm,
                          uint32_t* __restrict__ hi, uint32_t* __restrict__ lo, int N, int n)
{
    int i = blockIdx.x * blockDim.x + threadIdx.x;
    if (i >= n) return;
    int p = i / N, c = i - p * N;
    uint32_t l, h = split_pack(Bm[(size_t)(2 * p) * N + c], Bm[(size_t)(2 * p + 1) * N + c], l);
    hi[i] = h; lo[i] = l;
}

// ---------------- bf16x3 GEMM ----------------
__device__ __forceinline__ void mma_bf16(float* c, const uint32_t* a, uint32_t b0, uint32_t b1)
{
    asm("mma.sync.aligned.m16n8k16.row.col.f32.bf16.bf16.f32 "
        "{%0,%1,%2,%3}, {%4,%5,%6,%7}, {%8,%9}, {%0,%1,%2,%3};"
        : "+f"(c[0]), "+f"(c[1]), "+f"(c[2]), "+f"(c[3])
        : "r"(a[0]), "r"(a[1]), "r"(a[2]), "r"(a[3]), "r"(b0), "r"(b1));
}

__global__ __launch_bounds__(256, 2) void gemm_pre(
    const uint32_t* __restrict__ Ahi, const uint32_t* __restrict__ Alo,
    const uint32_t* __restrict__ Bhi, const uint32_t* __restrict__ Blo,
    const float* __restrict__ bias, float* __restrict__ C,
    int M, int N, int K)
{
    __shared__ uint32_t AsH[128][20];
    __shared__ uint32_t AsL[128][20];
    __shared__ uint32_t BsH[16][136];
    __shared__ uint32_t BsL[16][136];
    int tid = threadIdx.x;
    int wid = tid >> 5, lane = tid & 31;
    int g = lane >> 2, t = lane & 3;
    int wm = wid & 1, wn = wid >> 1;
    int cCol = blockIdx.x, cRow = blockIdx.y;
    const int KP = K >> 1;

    float acc[4][4][4];
#pragma unroll
    for (int i = 0; i < 4; i++)
#pragma unroll
        for (int j = 0; j < 4; j++)
#pragma unroll
            for (int c = 0; c < 4; c++) acc[i][j][c] = 0.f;

    for (int k0p = 0; k0p < KP; k0p += 16) {
#pragma unroll
        for (int j = 0; j < 4; j++) {
            int f = tid + 256 * j;
            int r = f >> 3, p2 = (f & 7) * 2;
            size_t off = (size_t)(cRow * 128 + r) * KP + k0p + p2;
            uint2 h = *(const uint2*)&Ahi[off];
            uint2 l = *(const uint2*)&Alo[off];
            AsH[r][p2] = h.x; AsH[r][p2 + 1] = h.y;
            AsL[r][p2] = l.x; AsL[r][p2 + 1] = l.y;
        }
#pragma unroll
        for (int j = 0; j < 4; j++) {
            int f = tid + 256 * j;
            int pr = f >> 6, c2 = (f & 63) * 2;
            size_t off = (size_t)(k0p + pr) * N + cCol * 128 + c2;
            uint2 h = *(const uint2*)&Bhi[off];
            uint2 l = *(const uint2*)&Blo[off];
            BsH[pr][c2] = h.x; BsH[pr][c2 + 1] = h.y;
            BsL[pr][c2] = l.x; BsL[pr][c2 + 1] = l.y;
        }
        __syncthreads();

#pragma unroll
        for (int kk = 0; kk < 2; kk++) {
            uint32_t ah[4][4], al[4][4];
#pragma unroll
            for (int mi = 0; mi < 4; mi++) {
                int ar = wm * 64 + mi * 16 + g;
                int pc = kk * 8 + t;
                ah[mi][0] = AsH[ar][pc];         al[mi][0] = AsL[ar][pc];
                ah[mi][1] = AsH[ar + 8][pc];     al[mi][1] = AsL[ar + 8][pc];
                ah[mi][2] = AsH[ar][pc + 4];     al[mi][2] = AsL[ar][pc + 4];
                ah[mi][3] = AsH[ar + 8][pc + 4]; al[mi][3] = AsL[ar + 8][pc + 4];
            }
#pragma unroll
            for (int ni = 0; ni < 4; ni++) {
                int bc = wn * 32 + ni * 8 + g;
                int pr = kk * 8 + t;
                uint32_t bh0 = BsH[pr][bc], bh1 = BsH[pr + 4][bc];
                uint32_t bl0 = BsL[pr][bc], bl1 = BsL[pr + 4][bc];
#pragma unroll
                for (int mi = 0; mi < 4; mi++) {
                    mma_bf16(acc[mi][ni], ah[mi], bh0, bh1);
                    mma_bf16(acc[mi][ni], al[mi], bh0, bh1);
                    mma_bf16(acc[mi][ni], ah[mi], bl0, bl1);
                }
            }
        }
        __syncthreads();
    }

#pragma unroll
    for (int mi = 0; mi < 4; mi++) {
#pragma unroll
        for (int ni = 0; ni < 4; ni++) {
            int r0 = cRow * 128 + wm * 64 + mi * 16 + g;
            int c0 = cCol * 128 + wn * 32 + ni * 8 + 2 * t;
            float b0 = bias ? bias[c0] : 0.f;
            float b1 = bias ? bias[c0 + 1] : 0.f;
            float2 v01 = make_float2(acc[mi][ni][0] + b0, acc[mi][ni][1] + b1);
            float2 v23 = make_float2(acc[mi][ni][2] + b0, acc[mi][ni][3] + b1);
            *(float2*)&C[(size_t)r0 * N + c0] = v01;
            *(float2*)&C[(size_t)(r0 + 8) * N + c0] = v23;
        }
    }
}

// ---------------- K2: orientation bins (2 k rows per thread) --------------
// grid (NSPLIT, H, B), block 64; thread t -> k = t, t+64
__global__ __launch_bounds__(64) void k2_scores()
{
    int t = threadIdx.x;
    int xc = blockIdx.x, h = blockIdx.y, b = blockIdx.z;
    int bh = b * H_ + h;
    int xbase = xc * (XL / NSPLIT);
    __shared__ float kx_sh[64 * 32];
    __shared__ unsigned pk_sh[128 * 33];

    uint64_t kqa[16], kqb[16];
    {
        const uint64_t* pa = (const uint64_t*)&g_QKVk[((size_t)(b * KL + t)) * TDIM + h * HD];
        const uint64_t* pb = (const uint64_t*)&g_QKVk[((size_t)(b * KL + t + 64)) * TDIM + h * HD];
#pragma unroll
        for (int i = 0; i < 16; i++) { kqa[i] = pa[i]; kqb[i] = pb[i]; }
    }

    float binsA[8], binsB[8];
#pragma unroll
    for (int o = 0; o < 8; o++) { binsA[o] = 0.f; binsB[o] = 0.f; }

    const unsigned* pkg = (const unsigned*)&g_rp[(size_t)b * KL * XL];

    for (int c = 0; c < 2; c++) {
        int xs = xbase + c * 64;
        __syncthreads();
        for (int g = t; g < 512; g += 64) {
            int row = g >> 3, c4 = g & 7;
            ((float4*)kx_sh)[g] =
                *(const float4*)&g_QKVx[((size_t)(b * XL + xs + row)) * TDIM + DIM + h * HD + c4 * 4];
        }
        for (int g = t; g < 1024; g += 64) {      // 128 rows x 8 uint4
            int row = g >> 3, q = g & 7;
            uint4 v = *(const uint4*)&pkg[(size_t)row * (XL / 2) + (xs >> 1) + q * 4];
            pk_sh[row * 33 + q * 4 + 0] = v.x;
            pk_sh[row * 33 + q * 4 + 1] = v.y;
            pk_sh[row * 33 + q * 4 + 2] = v.z;
            pk_sh[row * 33 + q * 4 + 3] = v.w;
        }
        __syncthreads();
        const unsigned short* prA = (const unsigned short*)&pk_sh[t * 33];
        const unsigned short* prB = (const unsigned short*)&pk_sh[(t + 64) * 33];
        for (int j = 0; j < 64; j++) {
            const ulonglong2* kx2 = (const ulonglong2*)&kx_sh[j * 32];
            uint64_t sa = 0, sb = 0;
#pragma unroll
            for (int d = 0; d < 8; d++) {
                ulonglong2 v = kx2[d];
                fma2(sa, kqa[2 * d], v.x);
                fma2(sa, kqa[2 * d + 1], v.y);
                fma2(sb, kqb[2 * d], v.x);
                fma2(sb, kqb[2 * d + 1], v.y);
            }
            float a0, a1, b0, b1;
            upk2(a0, a1, sa);
            upk2(b0, b1, sb);
            float asA = fabsf((a0 + a1) * SCALE);
            float asB = fabsf((b0 + b1) * SCALE);
            int pvA = (prA[j] >> 7) & 7;
            int pvB = (prB[j] >> 7) & 7;
#pragma unroll
            for (int o = 0; o < 8; o++) {
                binsA[o] += (pvA == o) ? asA : 0.f;
                binsB[o] += (pvB == o) ? asB : 0.f;
            }
        }
    }
    float* oA = &g_oriP[((size_t)xc * B_ * H_ * KL + bh * KL + t) * 8];
    float* oB = &g_oriP[((size_t)xc * B_ * H_ * KL + bh * KL + t + 64) * 8];
#pragma unroll
    for (int o = 0; o < 8; o++) { oA[o] = binsA[o]; oB[o] = binsB[o]; }
}

// ---------------- K2c: reduce slices + argmax ----------------
__global__ void k2_argmax()
{
    int idx = blockIdx.x * blockDim.x + threadIdx.x;
    if (idx >= B_ * H_ * KL) return;
    float s[8];
#pragma unroll
    for (int o = 0; o < 8; o++) s[o] = 0.f;
    for (int xc = 0; xc < NSPLIT; xc++) {
        const float* p = &g_oriP[((size_t)xc * B_ * H_ * KL + idx) * 8];
#pragma unroll
        for (int o = 0; o < 8; o++) s[o] += p[o];
    }
    int best = 0;
    float bv = s[0];
#pragma unroll
    for (int p = 1; p < 8; p++)
        if (s[p] > bv) { bv = s[p]; best = p; }
    g_mo[idx] = best;
}

// ---------------- K3: kernel->x attention (2 k rows per thread) -----------
// grid (NSPLIT, H, B), block 64; thread t -> k = t, t+64
__global__ __launch_bounds__(64) void k3_kattn(
    const float* __restrict__ dis_embed, const float* __restrict__ polar_emb)
{
    int t = threadIdx.x;
    int xs = blockIdx.x, h = blockIdx.y, b = blockIdx.z;
    int bh = b * H_ + h;
    __shared__ float kx_sh[64 * 32];
    __shared__ float V_sh[64 * 32];
    __shared__ unsigned pk_sh[128 * 33];
    __shared__ float de_sh[NDIS];
    __shared__ float pe_sh[8];
    for (int i = t; i < NDIS; i += 64) de_sh[i] = dis_embed[i * H_ + h];
    if (t < 8) pe_sh[t] = polar_emb[t];
    int moA = g_mo[bh * KL + t];
    int moB = g_mo[bh * KL + t + 64];

    uint64_t kqa[16], kqb[16];
    {
        const uint64_t* pa = (const uint64_t*)&g_QKVk[((size_t)(b * KL + t)) * TDIM + h * HD];
        const uint64_t* pb = (const uint64_t*)&g_QKVk[((size_t)(b * KL + t + 64)) * TDIM + h * HD];
#pragma unroll
        for (int i = 0; i < 16; i++) { kqa[i] = pa[i]; kqb[i] = pb[i]; }
    }

    const unsigned* pkg = (const unsigned*)&g_rp[(size_t)b * KL * XL];
    const uint8_t* mrA = &g_mb[((size_t)bh * KL + t) * (XL / 8)];
    const uint8_t* mrB = &g_mb[((size_t)bh * KL + t + 64) * (XL / 8)];

    float lA = 0.f, lB = 0.f;
    uint64_t accA[16], accB[16];
#pragma unroll
    for (int d = 0; d < 16; d++) { accA[d] = 0; accB[d] = 0; }

    int xbase = xs * (XL / NSPLIT);
    for (int c = 0; c < 2; c++) {
        int x0 = xbase + c * 64;
        uint64_t mbA = *(const uint64_t*)&mrA[x0 >> 3];
        uint64_t mbB = *(const uint64_t*)&mrB[x0 >> 3];
        __syncthreads();
        for (int g = t; g < 512; g += 64) {
            int row = g >> 3, c4 = g & 7;
            size_t rb = ((size_t)(b * XL + x0 + row)) * TDIM + h * HD + c4 * 4;
            ((float4*)kx_sh)[g] = *(const float4*)&g_QKVx[rb + DIM];
            ((float4*)V_sh)[g]  = *(const float4*)&g_QKVx[rb + 2 * DIM];
        }
        for (int g = t; g < 1024; g += 64) {
            int row = g >> 3, q = g & 7;
            uint4 v = *(const uint4*)&pkg[(size_t)row * (XL / 2) + (x0 >> 1) + q * 4];
            pk_sh[row * 33 + q * 4 + 0] = v.x;
            pk_sh[row * 33 + q * 4 + 1] = v.y;
            pk_sh[row * 33 + q * 4 + 2] = v.z;
            pk_sh[row * 33 + q * 4 + 3] = v.w;
        }
        __syncthreads();
        const unsigned short* prA = (const unsigned short*)&pk_sh[t * 33];
        const unsigned short* prB = (const unsigned short*)&pk_sh[(t + 64) * 33];
        for (int j = 0; j < 64; j++) {
            const ulonglong2* kx2 = (const ulonglong2*)&kx_sh[j * 32];
            uint64_t sa = 0, sb = 0;
#pragma unroll
            for (int d = 0; d < 8; d++) {
                ulonglong2 v = kx2[d];
                fma2(sa, kqa[2 * d], v.x);
                fma2(sa, kqa[2 * d + 1], v.y);
                fma2(sb, kqb[2 * d], v.x);
                fma2(sb, kqb[2 * d + 1], v.y);
            }
            float a0, a1, b0, b1;
            upk2(a0, a1, sa);
            upk2(b0, b1, sb);
            unsigned short pA = prA[j], pB = prB[j];
            float tA = (a0 + a1) * SCALE + de_sh[pA & 127] + pe_sh[(((pA >> 7) & 7) - moA) & 7];
            float tB = (b0 + b1) * SCALE + de_sh[pB & 127] + pe_sh[(((pB >> 7) & 7) - moB) & 7];
            float wA = ((mbA >> j) & 1) ? 0.f : __expf(tA);
            float wB = ((mbB >> j) & 1) ? 0.f : __expf(tB);
            lA += wA;
            lB += wB;
            uint64_t wpA = pk2(wA, wA), wpB = pk2(wB, wB);
            const ulonglong2* vp = (const ulonglong2*)&V_sh[j * 32];
#pragma unroll
            for (int d = 0; d < 8; d++) {
                ulonglong2 v = vp[d];
                fma2(accA[2 * d], wpA, v.x);
                fma2(accA[2 * d + 1], wpA, v.y);
                fma2(accB[2 * d], wpB, v.x);
                fma2(accB[2 * d + 1], wpB, v.y);
            }
        }
    }
    float* ppA = &g_part[(((size_t)bh * NSPLIT + xs) * KL + t) * 33];
    float* ppB = &g_part[(((size_t)bh * NSPLIT + xs) * KL + t + 64) * 33];
    ppA[0] = lA;
    ppB[0] = lB;
#pragma unroll
    for (int d = 0; d < 16; d++) {
        float a0, a1, b0, b1;
        upk2(a0, a1, accA[d]);
        upk2(b0, b1, accB[d]);
        ppA[1 + 2 * d] = a0; ppA[2 + 2 * d] = a1;
        ppB[1 + 2 * d] = b0; ppB[2 + 2 * d] = b1;
    }
}

// ---------------- K3c: combine x-splits -> preK (bf16 hi/lo out) ----------
__global__ void k3_combine()
{
    int idx = blockIdx.x * blockDim.x + threadIdx.x;
    if (idx >= B_ * H_ * KL * 16) return;
    int d2 = idx & 15;
    int k = (idx >> 4) & (KL - 1);
    int bh = idx >> 11;
    int h = bh % H_, b = bh / H_;
    const float* base = &g_part[((size_t)bh * NSPLIT) * KL * 33 + (size_t)k * 33];
    float L = 0.f, A0 = 0.f, A1 = 0.f;
    const size_t SSTR = (size_t)KL * 33;
#pragma unroll 8
    for (int s = 0; s < NSPLIT; s++) {
        L  += base[s * SSTR];
        A0 += base[s * SSTR + 1 + 2 * d2];
        A1 += base[s * SSTR + 2 + 2 * d2];
    }
    float invL = 1.f / L;
    uint32_t lo, hi = split_pack(A0 * invL, A1 * invL, lo);
    size_t o = ((size_t)b * KL + k) * (DIM / 2) + h * (HD / 2) + d2;
    g_pKh[o] = hi;
    g_pKl[o] = lo;
}

// ---------------- K4: x->kernel attention (2 x cols per thread) -----------
// grid (XL/256, H, B), block 128; thread t -> x = xc*256+t, +128
__global__ __launch_bounds__(128) void k4_xattn(
    const float* __restrict__ dis_embed, const float* __restrict__ polar_emb)
{
    __shared__ float kk_sh[KL * HD];
    __shared__ float kv_sh[KL * HD];
    __shared__ uint32_t mb_sh[KL][8];    // 256 mask bits per k row
    __shared__ float de_sh[NDIS];
    __shared__ float pe_sh[8];
    __shared__ int   mo_sh[KL];
    int tid = threadIdx.x;
    int xc = blockIdx.x, h = blockIdx.y, b = blockIdx.z;
    int bh = b * H_ + h;

    for (int g = tid; g < KL * HD / 4; g += 128) {
        int row = g >> 3, c4 = g & 7;
        ((float4*)kk_sh)[g] =
            *(const float4*)&g_QKVk[((size_t)(b * KL + row)) * TDIM + DIM + h * HD + c4 * 4];
        ((float4*)kv_sh)[g] =
            *(const float4*)&g_QKVk[((size_t)(b * KL + row)) * TDIM + 2 * DIM + h * HD + c4 * 4];
    }
    for (int g = tid; g < 256; g += 128) {
        int row = g >> 1, half = g & 1;
        *(uint4*)&mb_sh[row][half * 4] =
            *(const uint4*)&g_mb[((size_t)bh * KL + row) * (XL / 8) + xc * 32 + half * 16];
    }
    if (tid < NDIS) de_sh[tid] = dis_embed[tid * H_ + h];
    if (tid < 8) pe_sh[tid] = polar_emb[tid];
    if (tid < KL) mo_sh[tid] = g_mo[bh * KL + tid];
    __syncthreads();

    int xA = xc * 256 + tid;
    int xB = xA + 128;
    int wsel = tid >> 5, bsel = tid & 31;
    uint64_t qA[16], qB[16];
    {
        const uint64_t* pa = (const uint64_t*)&g_QKVx[((size_t)(b * XL + xA)) * TDIM + h * HD];
        const uint64_t* pb = (const uint64_t*)&g_QKVx[((size_t)(b * XL + xB)) * TDIM + h * HD];
#pragma unroll
        for (int i = 0; i < 16; i++) { qA[i] = pa[i]; qB[i] = pb[i]; }
    }
    const unsigned short* rpA = &g_rp[(size_t)b * KL * XL + xA];

    float lA = 0.f, lB = 0.f;
    uint64_t accA[16], accB[16];
#pragma unroll
    for (int d = 0; d < 16; d++) { accA[d] = 0; accB[d] = 0; }

    for (int kidx = 0; kidx < KL; kidx++) {
        const ulonglong2* kkp = (const ulonglong2*)&kk_sh[kidx * HD];
        uint64_t sa = 0, sb = 0;
#pragma unroll
        for (int d = 0; d < 8; d++) {
            ulonglong2 v = kkp[d];
            fma2(sa, qA[2 * d], v.x);
            fma2(sa, qA[2 * d + 1], v.y);
            fma2(sb, qB[2 * d], v.x);
            fma2(sb, qB[2 * d + 1], v.y);
        }
        float a0, a1, b0, b1;
        upk2(a0, a1, sa);
        upk2(b0, b1, sb);
        unsigned short pA = rpA[(size_t)kidx * XL];
        unsigned short pB = rpA[(size_t)kidx * XL + 128];
        int mo = mo_sh[kidx];
        float tA = (a0 + a1) * SCALE + de_sh[pA & 127] + pe_sh[(((pA >> 7) & 7) - mo) & 7];
        float tB = (b0 + b1) * SCALE + de_sh[pB & 127] + pe_sh[(((pB >> 7) & 7) - mo) & 7];
        float wA = ((mb_sh[kidx][wsel] >> bsel) & 1u) ? 0.f : __expf(tA);
        float wB = ((mb_sh[kidx][4 + wsel] >> bsel) & 1u) ? 0.f : __expf(tB);
        lA += wA;
        lB += wB;
        uint64_t wpA = pk2(wA, wA), wpB = pk2(wB, wB);
        const ulonglong2* vp = (const ulonglong2*)&kv_sh[kidx * HD];
#pragma unroll
        for (int d = 0; d < 8; d++) {
            ulonglong2 v = vp[d];
            fma2(accA[2 * d], wpA, v.x);
            fma2(accA[2 * d + 1], wpA, v.y);
            fma2(accB[2 * d], wpB, v.x);
            fma2(accB[2 * d + 1], wpB, v.y);
        }
    }
    float invA = 1.f / lA, invB = 1.f / lB;
    size_t obA = ((size_t)(b * XL + xA)) * (DIM / 2) + h * (HD / 2);
    size_t obB = ((size_t)(b * XL + xB)) * (DIM / 2) + h * (HD / 2);
#pragma unroll
    for (int d2 = 0; d2 < 16; d2++) {
        float a0, a1, b0, b1;
        upk2(a0, a1, accA[d2]);
        upk2(b0, b1, accB[d2]);
        uint32_t loA, hiA = split_pack(a0 * invA, a1 * invA, loA);
        uint32_t loB, hiB = split_pack(b0 * invB, b1 * invB, loB);
        g_pXh[obA + d2] = hiA; g_pXl[obA + d2] = loA;
        g_pXh[obB + d2] = hiB; g_pXl[obB + d2] = loB;
    }
}

// ---------------- host launcher ----------------
extern "C" void kernel_launch(void* const* d_in, const int* in_sizes, int n_in,
                              void* d_out, int out_size)
{
    const float* x     = (const float*)d_in[0];
    const float* kern  = (const float*)d_in[1];
    const int*   rd    = (const int*)d_in[2];
    const int*   polar = (const int*)d_in[3];
    const void*  mask  = d_in[4];
    const float* Wqkv  = (const float*)d_in[5];
    const float* dis   = (const float*)d_in[6];
    const float* pemb  = (const float*)d_in[7];
    const float* Wproj = (const float*)d_in[8];
    const float* bproj = (const float*)d_in[9];
    float* out = (float*)d_out;

    float* pQKVx; cudaGetSymbolAddress((void**)&pQKVx, g_QKVx);
    float* pQKVk; cudaGetSymbolAddress((void**)&pQKVk, g_QKVk);
    uint32_t *pxh, *pxl, *pkh, *pkl, *pwqh, *pwql, *pwph, *pwpl, *pXh, *pXl, *pKh, *pKl;
    cudaGetSymbolAddress((void**)&pxh, g_xhi);  cudaGetSymbolAddress((void**)&pxl, g_xlo);
    cudaGetSymbolAddress((void**)&pkh, g_khi);  cudaGetSymbolAddress((void**)&pkl, g_klo);
    cudaGetSymbolAddress((void**)&pwqh, g_wqh); cudaGetSymbolAddress((void**)&pwql, g_wql);
    cudaGetSymbolAddress((void**)&pwph, g_wph); cudaGetSymbolAddress((void**)&pwpl, g_wpl);
    cudaGetSymbolAddress((void**)&pXh, g_pXh);  cudaGetSymbolAddress((void**)&pXl, g_pXl);
    cudaGetSymbolAddress((void**)&pKh, g_pKh);  cudaGetSymbolAddress((void**)&pKl, g_pKl);

    // mask dtype probe + compact bias/mask tables
    det_reset<<<1, 32>>>();
    det_scan<<<256, 256>>>((const unsigned*)mask);
    rp16<<<(B_ * KL * XL / 2 + 255) / 256, 256>>>(rd, polar);
    maskbit<<<dim3(XL / 64, KL / 32, B_), dim3(32, 8)>>>(mask);

    // pre-split GEMM operands
    presplitA<<<(B_ * XL * DIM / 2 + 255) / 256, 256>>>(x, pxh, pxl, B_ * XL * DIM / 2);
    presplitA<<<(B_ * KL * DIM / 2 + 255) / 256, 256>>>(kern, pkh, pkl, B_ * KL * DIM / 2);
    presplitB<<<((DIM / 2) * TDIM + 255) / 256, 256>>>(Wqkv, pwqh, pwql, TDIM, (DIM / 2) * TDIM);
    presplitB<<<((DIM / 2) * DIM + 255) / 256, 256>>>(Wproj, pwph, pwpl, DIM, (DIM / 2) * DIM);

    // QKV projections
    gemm_pre<<<dim3(TDIM / 128, (B_ * XL) / 128), 256>>>(pxh, pxl, pwqh, pwql, nullptr, pQKVx, B_ * XL, TDIM, DIM);
    gemm_pre<<<dim3(TDIM / 128, (B_ * KL) / 128), 256>>>(pkh, pkl, pwqh, pwql, nullptr, pQKVk, B_ * KL, TDIM, DIM);

    // orientation bins + argmax
    k2_scores<<<dim3(NSPLIT, H_, B_), 64>>>();
    k2_argmax<<<(B_ * H_ * KL + 255) / 256, 256>>>();

    // kernel->x attention
    k3_kattn<<<dim3(NSPLIT, H_, B_), 64>>>(dis, pemb);
    k3_combine<<<(B_ * H_ * KL * 16 + 255) / 256, 256>>>();

    // x->kernel attention
    k4_xattn<<<dim3(XL / 256, H_, B_), 128>>>(dis, pemb);

    // output projections
    gemm_pre<<<dim3(DIM / 128, (B_ * XL) / 128), 256>>>(pXh, pXl, pwph, pwpl, bproj, out, B_ * XL, DIM, DIM);
    gemm_pre<<<dim3(DIM / 128, (B_ * KL) / 128), 256>>>(pKh, pKl, pwph, pwpl, bproj, out + (size_t)B_ * XL * DIM, B_ * KL, DIM, DIM);
}

// round 15
// speedup vs baseline: 1.1568x; 1.0912x over previous
#include <cuda_runtime.h>
#include <cuda_bf16.h>
#include <cstdint>

#define B_    4
#define KL    128
#define XL    4096
#define DIM   256
#define H_    8
#define HD    32
#define PB    8
#define NDIS  66
#define TDIM  768           // 3*DIM
#define SCALE 0.17677669529663687f
#define NSPLIT 32           // x-splits for k2/k3

// ---------------- scratch (device globals) ----------------
__device__ float    g_QKVx[B_ * XL * TDIM];
__device__ float    g_QKVk[B_ * KL * TDIM];
__device__ unsigned short g_rp[(size_t)B_ * KL * XL];          // rd | polar<<7 (4 MB)
__device__ uint8_t  g_mb[(size_t)B_ * H_ * KL * (XL / 8)];     // transposed mask bits (2 MB)
__device__ float    g_oriP[NSPLIT * B_ * H_ * KL * PB];
__device__ int      g_mo[B_ * H_ * KL];
__device__ float    g_part[(size_t)B_ * H_ * NSPLIT * KL * 33];
__device__ unsigned g_flags;
// pre-split bf16 hi/lo operand storage (u32 = packed bf16x2)
__device__ uint32_t g_xhi[B_ * XL * DIM / 2],  g_xlo[B_ * XL * DIM / 2];
__device__ uint32_t g_khi[B_ * KL * DIM / 2],  g_klo[B_ * KL * DIM / 2];
__device__ uint32_t g_wqh[(DIM / 2) * TDIM],   g_wql[(DIM / 2) * TDIM];
__device__ uint32_t g_wph[(DIM / 2) * DIM],    g_wpl[(DIM / 2) * DIM];
__device__ uint32_t g_pXh[B_ * XL * DIM / 2],  g_pXl[B_ * XL * DIM / 2];
__device__ uint32_t g_pKh[B_ * KL * DIM / 2],  g_pKl[B_ * KL * DIM / 2];
// k3-mma operands
__device__ uint32_t g_kqh[B_ * H_ * KL * 16],  g_kql[B_ * H_ * KL * 16];   // [bh][k][dpair]
__device__ uint32_t g_kxh2[(size_t)B_ * H_ * 16 * XL], g_kxl2[(size_t)B_ * H_ * 16 * XL]; // [bh][dpair][x]
__device__ uint32_t g_vxh[(size_t)B_ * H_ * (XL / 2) * 32], g_vxl[(size_t)B_ * H_ * (XL / 2) * 32]; // [bh][xpair][d]

// ---------------- f32x2 packed helpers ----------------
__device__ __forceinline__ uint64_t pk2(float lo, float hi)
{
    uint64_t r;
    asm("mov.b64 %0, {%1, %2};" : "=l"(r) : "f"(lo), "f"(hi));
    return r;
}
__device__ __forceinline__ void upk2(float& lo, float& hi, uint64_t v)
{
    asm("mov.b64 {%0, %1}, %2;" : "=f"(lo), "=f"(hi) : "l"(v));
}
__device__ __forceinline__ void fma2(uint64_t& d, uint64_t a, uint64_t b)
{
    asm("fma.rn.f32x2 %0, %1, %2, %0;" : "+l"(d) : "l"(a), "l"(b));
}

// ---------------- bf16 split helper ----------------
__device__ __forceinline__ uint32_t split_pack(float x0, float x1, uint32_t& lo_pack)
{
    __nv_bfloat16 h0 = __float2bfloat16(x0);
    __nv_bfloat16 h1 = __float2bfloat16(x1);
    float l0 = x0 - __bfloat162float(h0);
    float l1 = x1 - __bfloat162float(h1);
    __nv_bfloat162 hp = __halves2bfloat162(h0, h1);
    __nv_bfloat162 lp = __halves2bfloat162(__float2bfloat16(l0), __float2bfloat16(l1));
    lo_pack = *(uint32_t*)&lp;
    return *(uint32_t*)&hp;
}

// ---------------- mask dtype probe ----------------
__global__ void det_reset() { if (threadIdx.x == 0) g_flags = 0u; }

__global__ void det_scan(const unsigned* __restrict__ w)
{
    int i = blockIdx.x * blockDim.x + threadIdx.x;
    unsigned v = w[i];
    unsigned f = 0;
    if (v == 0x3F800000u) f |= 1u;
    else if (v != 0u && v != 1u) f |= 2u;
    for (int o = 16; o > 0; o >>= 1) f |= __shfl_xor_sync(0xffffffffu, f, o);
    if ((threadIdx.x & 31) == 0 && f) atomicOr(&g_flags, f);
}

// ---------------- rp16 ----------------
__global__ void rp16(const int* __restrict__ rd, const int* __restrict__ polar)
{
    int i = blockIdx.x * blockDim.x + threadIdx.x;
    if (i >= B_ * KL * XL / 2) return;
    int2 r = *(const int2*)&rd[2 * i];
    int2 p = *(const int2*)&polar[2 * i];
    unsigned lo = (unsigned)(r.x | (p.x << 7));
    unsigned hi = (unsigned)(r.y | (p.y << 7));
    ((unsigned*)g_rp)[i] = lo | (hi << 16);
}

// ---------------- maskbit ----------------
__global__ void maskbit(const void* __restrict__ mask)
{
    __shared__ uint8_t m_sh[64][36];
    unsigned flags = g_flags;
    int mode = (flags & 1u) ? 2 : ((flags & 2u) ? 0 : 1);
    int x0 = blockIdx.x * 64, k0 = blockIdx.y * 32, b = blockIdx.z;
    int tx = threadIdx.x, ty = threadIdx.y;
    int tid = ty * 32 + tx;
    int ki = tid >> 3, jb = tid & 7;

    for (int h = 0; h < H_; h++) {
        size_t mb = ((size_t)((b * H_ + h)) * XL + x0) * KL + k0;
#pragma unroll
        for (int xi = ty; xi < 64; xi += 8) {
            uint8_t v;
            if (mode == 1)      v = ((const int*)mask)[mb + (size_t)xi * KL + tx] != 0;
            else if (mode == 2) v = ((const float*)mask)[mb + (size_t)xi * KL + tx] != 0.f;
            else                v = ((const uint8_t*)mask)[mb + (size_t)xi * KL + tx] != 0;
            m_sh[xi][tx] = v;
        }
        __syncthreads();
        uint8_t byte = 0;
#pragma unroll
        for (int i = 0; i < 8; i++)
            byte |= (uint8_t)(m_sh[8 * jb + i][ki] << i);
        g_mb[((size_t)((b * H_ + h) * KL + k0 + ki)) * (XL / 8) + (x0 >> 3) + jb] = byte;
        __syncthreads();
    }
}

// ---------------- presplit kernels (GEMM operands) ----------------
__global__ void presplitA(const float* __restrict__ A,
                          uint32_t* __restrict__ hi, uint32_t* __restrict__ lo, int n)
{
    int i = blockIdx.x * blockDim.x + threadIdx.x;
    if (i >= n) return;
    float2 v = *(const float2*)&A[2 * i];
    uint32_t l, h = split_pack(v.x, v.y, l);
    hi[i] = h; lo[i] = l;
}

__global__ void presplitB(const float* __restrict__ Bm,
                          uint32_t* __restrict__ hi, uint32_t* __restrict__ lo, int N, int n)
{
    int i = blockIdx.x * blockDim.x + threadIdx.x;
    if (i >= n) return;
    int p = i / N, c = i - p * N;
    uint32_t l, h = split_pack(Bm[(size_t)(2 * p) * N + c], Bm[(size_t)(2 * p + 1) * N + c], l);
    hi[i] = h; lo[i] = l;
}

// ---------------- prep for k3-mma ----------------
// kq: [bh][k][dpair], pairs along d
__global__ void prep_kq()
{
    int i = blockIdx.x * blockDim.x + threadIdx.x;
    if (i >= B_ * H_ * KL * 16) return;
    int dp = i & 15;
    int k = (i >> 4) & (KL - 1);
    int bh = i >> 11;
    int b = bh >> 3, h = bh & 7;
    const float* src = &g_QKVk[((size_t)(b * KL + k)) * TDIM + h * HD + 2 * dp];
    uint32_t l, hh = split_pack(src[0], src[1], l);
    g_kqh[i] = hh;
    g_kql[i] = l;
}

// kx: [bh][dpair][x] (pairs along d); v: [bh][xpair][d] (pairs along x)
// grid (XL/64, H, B), block 128
__global__ __launch_bounds__(128) void prep_kxv()
{
    __shared__ float kx_sh[64][33];
    __shared__ float v_sh[64][33];
    int tid = threadIdx.x;
    int xt = blockIdx.x, h = blockIdx.y, b = blockIdx.z;
    int bh = b * H_ + h;
    int x0 = xt * 64;

    for (int g = tid; g < 512; g += 128) {
        int row = g >> 3, c4 = g & 7;
        size_t rb = ((size_t)(b * XL + x0 + row)) * TDIM + h * HD + c4 * 4;
        float4 a = *(const float4*)&g_QKVx[rb + DIM];
        float4 v = *(const float4*)&g_QKVx[rb + 2 * DIM];
        kx_sh[row][c4 * 4 + 0] = a.x; kx_sh[row][c4 * 4 + 1] = a.y;
        kx_sh[row][c4 * 4 + 2] = a.z; kx_sh[row][c4 * 4 + 3] = a.w;
        v_sh[row][c4 * 4 + 0] = v.x;  v_sh[row][c4 * 4 + 1] = v.y;
        v_sh[row][c4 * 4 + 2] = v.z;  v_sh[row][c4 * 4 + 3] = v.w;
    }
    __syncthreads();
#pragma unroll
    for (int i = 0; i < 8; i++) {
        int e = tid + 128 * i;
        int dp = e >> 6, xx = e & 63;
        uint32_t l, hh = split_pack(kx_sh[xx][2 * dp], kx_sh[xx][2 * dp + 1], l);
        size_t o = ((size_t)bh * 16 + dp) * XL + x0 + xx;
        g_kxh2[o] = hh;
        g_kxl2[o] = l;
    }
#pragma unroll
    for (int i = 0; i < 8; i++) {
        int e = tid + 128 * i;
        int xp = e >> 5, d = e & 31;
        uint32_t l, hh = split_pack(v_sh[2 * xp][d], v_sh[2 * xp + 1][d], l);
        size_t o = ((size_t)bh * (XL / 2) + (x0 >> 1) + xp) * 32 + d;
        g_vxh[o] = hh;
        g_vxl[o] = l;
    }
}

// ---------------- bf16x3 GEMM ----------------
__device__ __forceinline__ void mma_bf16(float* c, const uint32_t* a, uint32_t b0, uint32_t b1)
{
    asm("mma.sync.aligned.m16n8k16.row.col.f32.bf16.bf16.f32 "
        "{%0,%1,%2,%3}, {%4,%5,%6,%7}, {%8,%9}, {%0,%1,%2,%3};"
        : "+f"(c[0]), "+f"(c[1]), "+f"(c[2]), "+f"(c[3])
        : "r"(a[0]), "r"(a[1]), "r"(a[2]), "r"(a[3]), "r"(b0), "r"(b1));
}

__global__ __launch_bounds__(256, 2) void gemm_pre(
    const uint32_t* __restrict__ Ahi, const uint32_t* __restrict__ Alo,
    const uint32_t* __restrict__ Bhi, const uint32_t* __restrict__ Blo,
    const float* __restrict__ bias, float* __restrict__ C,
    int M, int N, int K)
{
    __shared__ uint32_t AsH[128][20];
    __shared__ uint32_t AsL[128][20];
    __shared__ uint32_t BsH[16][136];
    __shared__ uint32_t BsL[16][136];
    int tid = threadIdx.x;
    int wid = tid >> 5, lane = tid & 31;
    int g = lane >> 2, t = lane & 3;
    int wm = wid & 1, wn = wid >> 1;
    int cCol = blockIdx.x, cRow = blockIdx.y;
    const int KP = K >> 1;

    float acc[4][4][4];
#pragma unroll
    for (int i = 0; i < 4; i++)
#pragma unroll
        for (int j = 0; j < 4; j++)
#pragma unroll
            for (int c = 0; c < 4; c++) acc[i][j][c] = 0.f;

    for (int k0p = 0; k0p < KP; k0p += 16) {
#pragma unroll
        for (int j = 0; j < 4; j++) {
            int f = tid + 256 * j;
            int r = f >> 3, p2 = (f & 7) * 2;
            size_t off = (size_t)(cRow * 128 + r) * KP + k0p + p2;
            uint2 h = *(const uint2*)&Ahi[off];
            uint2 l = *(const uint2*)&Alo[off];
            AsH[r][p2] = h.x; AsH[r][p2 + 1] = h.y;
            AsL[r][p2] = l.x; AsL[r][p2 + 1] = l.y;
        }
#pragma unroll
        for (int j = 0; j < 4; j++) {
            int f = tid + 256 * j;
            int pr = f >> 6, c2 = (f & 63) * 2;
            size_t off = (size_t)(k0p + pr) * N + cCol * 128 + c2;
            uint2 h = *(const uint2*)&Bhi[off];
            uint2 l = *(const uint2*)&Blo[off];
            BsH[pr][c2] = h.x; BsH[pr][c2 + 1] = h.y;
            BsL[pr][c2] = l.x; BsL[pr][c2 + 1] = l.y;
        }
        __syncthreads();

#pragma unroll
        for (int kk = 0; kk < 2; kk++) {
            uint32_t ah[4][4], al[4][4];
#pragma unroll
            for (int mi = 0; mi < 4; mi++) {
                int ar = wm * 64 + mi * 16 + g;
                int pc = kk * 8 + t;
                ah[mi][0] = AsH[ar][pc];         al[mi][0] = AsL[ar][pc];
                ah[mi][1] = AsH[ar + 8][pc];     al[mi][1] = AsL[ar + 8][pc];
                ah[mi][2] = AsH[ar][pc + 4];     al[mi][2] = AsL[ar][pc + 4];
                ah[mi][3] = AsH[ar + 8][pc + 4]; al[mi][3] = AsL[ar + 8][pc + 4];
            }
#pragma unroll
            for (int ni = 0; ni < 4; ni++) {
                int bc = wn * 32 + ni * 8 + g;
                int pr = kk * 8 + t;
                uint32_t bh0 = BsH[pr][bc], bh1 = BsH[pr + 4][bc];
                uint32_t bl0 = BsL[pr][bc], bl1 = BsL[pr + 4][bc];
#pragma unroll
                for (int mi = 0; mi < 4; mi++) {
                    mma_bf16(acc[mi][ni], ah[mi], bh0, bh1);
                    mma_bf16(acc[mi][ni], al[mi], bh0, bh1);
                    mma_bf16(acc[mi][ni], ah[mi], bl0, bl1);
                }
            }
        }
        __syncthreads();
    }

#pragma unroll
    for (int mi = 0; mi < 4; mi++) {
#pragma unroll
        for (int ni = 0; ni < 4; ni++) {
            int r0 = cRow * 128 + wm * 64 + mi * 16 + g;
            int c0 = cCol * 128 + wn * 32 + ni * 8 + 2 * t;
            float b0 = bias ? bias[c0] : 0.f;
            float b1 = bias ? bias[c0 + 1] : 0.f;
            float2 v01 = make_float2(acc[mi][ni][0] + b0, acc[mi][ni][1] + b1);
            float2 v23 = make_float2(acc[mi][ni][2] + b0, acc[mi][ni][3] + b1);
            *(float2*)&C[(size_t)r0 * N + c0] = v01;
            *(float2*)&C[(size_t)(r0 + 8) * N + c0] = v23;
        }
    }
}

// ---------------- K2: orientation bins (2 k rows per thread) --------------
__global__ __launch_bounds__(64) void k2_scores()
{
    int t = threadIdx.x;
    int xc = blockIdx.x, h = blockIdx.y, b = blockIdx.z;
    int bh = b * H_ + h;
    int xbase = xc * (XL / NSPLIT);
    __shared__ float kx_sh[64 * 32];
    __shared__ unsigned pk_sh[128 * 33];

    uint64_t kqa[16], kqb[16];
    {
        const uint64_t* pa = (const uint64_t*)&g_QKVk[((size_t)(b * KL + t)) * TDIM + h * HD];
        const uint64_t* pb = (const uint64_t*)&g_QKVk[((size_t)(b * KL + t + 64)) * TDIM + h * HD];
#pragma unroll
        for (int i = 0; i < 16; i++) { kqa[i] = pa[i]; kqb[i] = pb[i]; }
    }

    float binsA[8], binsB[8];
#pragma unroll
    for (int o = 0; o < 8; o++) { binsA[o] = 0.f; binsB[o] = 0.f; }

    const unsigned* pkg = (const unsigned*)&g_rp[(size_t)b * KL * XL];

    for (int c = 0; c < 2; c++) {
        int xs = xbase + c * 64;
        __syncthreads();
        for (int g = t; g < 512; g += 64) {
            int row = g >> 3, c4 = g & 7;
            ((float4*)kx_sh)[g] =
                *(const float4*)&g_QKVx[((size_t)(b * XL + xs + row)) * TDIM + DIM + h * HD + c4 * 4];
        }
        for (int g = t; g < 1024; g += 64) {
            int row = g >> 3, q = g & 7;
            uint4 v = *(const uint4*)&pkg[(size_t)row * (XL / 2) + (xs >> 1) + q * 4];
            pk_sh[row * 33 + q * 4 + 0] = v.x;
            pk_sh[row * 33 + q * 4 + 1] = v.y;
            pk_sh[row * 33 + q * 4 + 2] = v.z;
            pk_sh[row * 33 + q * 4 + 3] = v.w;
        }
        __syncthreads();
        const unsigned short* prA = (const unsigned short*)&pk_sh[t * 33];
        const unsigned short* prB = (const unsigned short*)&pk_sh[(t + 64) * 33];
        for (int j = 0; j < 64; j++) {
            const ulonglong2* kx2 = (const ulonglong2*)&kx_sh[j * 32];
            uint64_t sa = 0, sb = 0;
#pragma unroll
            for (int d = 0; d < 8; d++) {
                ulonglong2 v = kx2[d];
                fma2(sa, kqa[2 * d], v.x);
                fma2(sa, kqa[2 * d + 1], v.y);
                fma2(sb, kqb[2 * d], v.x);
                fma2(sb, kqb[2 * d + 1], v.y);
            }
            float a0, a1, b0, b1;
            upk2(a0, a1, sa);
            upk2(b0, b1, sb);
            float asA = fabsf((a0 + a1) * SCALE);
            float asB = fabsf((b0 + b1) * SCALE);
            int pvA = (prA[j] >> 7) & 7;
            int pvB = (prB[j] >> 7) & 7;
#pragma unroll
            for (int o = 0; o < 8; o++) {
                binsA[o] += (pvA == o) ? asA : 0.f;
                binsB[o] += (pvB == o) ? asB : 0.f;
            }
        }
    }
    float* oA = &g_oriP[((size_t)xc * B_ * H_ * KL + bh * KL + t) * 8];
    float* oB = &g_oriP[((size_t)xc * B_ * H_ * KL + bh * KL + t + 64) * 8];
#pragma unroll
    for (int o = 0; o < 8; o++) { oA[o] = binsA[o]; oB[o] = binsB[o]; }
}

// ---------------- K2c ----------------
__global__ void k2_argmax()
{
    int idx = blockIdx.x * blockDim.x + threadIdx.x;
    if (idx >= B_ * H_ * KL) return;
    float s[8];
#pragma unroll
    for (int o = 0; o < 8; o++) s[o] = 0.f;
    for (int xc = 0; xc < NSPLIT; xc++) {
        const float* p = &g_oriP[((size_t)xc * B_ * H_ * KL + idx) * 8];
#pragma unroll
        for (int o = 0; o < 8; o++) s[o] += p[o];
    }
    int best = 0;
    float bv = s[0];
#pragma unroll
    for (int p = 1; p < 8; p++)
        if (s[p] > bv) { bv = s[p]; best = p; }
    g_mo[idx] = best;
}

// ---------------- K3-MMA: kernel->x attention via tensor cores ------------
// grid (NSPLIT, H, B), block 128 (4 warps); warp w owns k rows [32w, 32w+32)
__global__ __launch_bounds__(128) void k3_mma(
    const float* __restrict__ dis_embed, const float* __restrict__ polar_emb)
{
    __shared__ uint32_t bxh[16][72], bxl[16][72];   // kx [dpair][x]
    __shared__ uint32_t vsh[32][40], vsl[32][40];   // v  [xpair][d]
    __shared__ uint32_t rp_sh[128 * 33];            // rp  [k][x-u32pair]
    __shared__ uint64_t mb_sh[128];                 // mask bits per k row
    __shared__ float de_sh[NDIS];
    __shared__ float pe_sh[8];

    int tid = threadIdx.x;
    int wid = tid >> 5, lane = tid & 31;
    int g = lane >> 2, t = lane & 3;
    int xc = blockIdx.x, h = blockIdx.y, b = blockIdx.z;
    int bh = b * H_ + h;
    int warpk = wid * 32;

    if (tid < NDIS) de_sh[tid] = dis_embed[tid * H_ + h];
    if (tid < 8) pe_sh[tid] = polar_emb[tid];

    // A-frags (kq), per warp 2 M-tiles x 2 k-chunks
    uint32_t aqh[2][2][4], aql[2][2][4];
    int mov[2][2];
#pragma unroll
    for (int m = 0; m < 2; m++) {
        int rA = warpk + m * 16 + g;
        int rB = rA + 8;
        mov[m][0] = g_mo[bh * KL + warpk + m * 16 + g - g + 0];   // placeholder, fixed below
#pragma unroll
        for (int c = 0; c < 2; c++) {
            size_t baseA = ((size_t)bh * KL + rA) * 16 + c * 8 + t;
            size_t baseB = ((size_t)bh * KL + rB) * 16 + c * 8 + t;
            aqh[m][c][0] = g_kqh[baseA];
            aqh[m][c][1] = g_kqh[baseB];
            aqh[m][c][2] = g_kqh[baseA + 4];
            aqh[m][c][3] = g_kqh[baseB + 4];
            aql[m][c][0] = g_kql[baseA];
            aql[m][c][1] = g_kql[baseB];
            aql[m][c][2] = g_kql[baseA + 4];
            aql[m][c][3] = g_kql[baseB + 4];
        }
        mov[m][0] = g_mo[bh * KL + rA];
        mov[m][1] = g_mo[bh * KL + rB];
    }

    float accd[2][4][4];
#pragma unroll
    for (int m = 0; m < 2; m++)
#pragma unroll
        for (int n = 0; n < 4; n++)
#pragma unroll
            for (int c = 0; c < 4; c++) accd[m][n][c] = 0.f;
    float lr[2][2] = {{0.f, 0.f}, {0.f, 0.f}};

    const unsigned* rp32 = (const unsigned*)g_rp;

    for (int xt = 0; xt < 2; xt++) {
        int x0 = xc * 128 + xt * 64;
        __syncthreads();
        // stage kx (B operand)
#pragma unroll
        for (int i = 0; i < 8; i++) {
            int e = tid + 128 * i;
            int dp = e >> 6, xx = e & 63;
            size_t o = ((size_t)bh * 16 + dp) * XL + x0 + xx;
            bxh[dp][xx] = g_kxh2[o];
            bxl[dp][xx] = g_kxl2[o];
        }
        // stage V
#pragma unroll
        for (int i = 0; i < 8; i++) {
            int e = tid + 128 * i;
            int xp = e >> 5, d = e & 31;
            size_t o = ((size_t)bh * (XL / 2) + (x0 >> 1) + xp) * 32 + d;
            vsh[xp][d] = g_vxh[o];
            vsl[xp][d] = g_vxl[o];
        }
        // stage rp
#pragma unroll
        for (int i = 0; i < 32; i++) {
            int e = tid + 128 * i;
            int row = e >> 5, col = e & 31;
            rp_sh[row * 33 + col] = rp32[(size_t)(b * KL + row) * (XL / 2) + (x0 >> 1) + col];
        }
        // stage mask bits
        mb_sh[tid] = *(const uint64_t*)&g_mb[((size_t)bh * KL + tid) * (XL / 8) + (x0 >> 3)];
        __syncthreads();

        // ---- mma1: S = KQ @ KX^T ----
        float sf[2][8][4];
#pragma unroll
        for (int m = 0; m < 2; m++)
#pragma unroll
            for (int j = 0; j < 8; j++) {
                sf[m][j][0] = sf[m][j][1] = sf[m][j][2] = sf[m][j][3] = 0.f;
#pragma unroll
                for (int c = 0; c < 2; c++) {
                    uint32_t b0h = bxh[c * 8 + t][j * 8 + g];
                    uint32_t b1h = bxh[c * 8 + t + 4][j * 8 + g];
                    uint32_t b0l = bxl[c * 8 + t][j * 8 + g];
                    uint32_t b1l = bxl[c * 8 + t + 4][j * 8 + g];
                    mma_bf16(sf[m][j], aqh[m][c], b0h, b1h);
                    mma_bf16(sf[m][j], aql[m][c], b0h, b1h);
                    mma_bf16(sf[m][j], aqh[m][c], b0l, b1l);
                }
            }

        // ---- epilogue + mma2 per m, x-chunk ----
#pragma unroll
        for (int m = 0; m < 2; m++) {
            int rA = warpk + m * 16 + g;
            int rB = rA + 8;
            uint64_t mA = mb_sh[rA];
            uint64_t mB = mb_sh[rB];
            int moA = mov[m][0], moB = mov[m][1];
#pragma unroll
            for (int cc = 0; cc < 4; cc++) {
                float wv[2][4];
#pragma unroll
                for (int jl = 0; jl < 2; jl++) {
                    int j = 2 * cc + jl;
                    unsigned rpA = rp_sh[rA * 33 + 4 * j + t];
                    unsigned rpB = rp_sh[rB * 33 + 4 * j + t];
                    float s0 = sf[m][j][0] * SCALE;
                    float s1 = sf[m][j][1] * SCALE;
                    float s2 = sf[m][j][2] * SCALE;
                    float s3 = sf[m][j][3] * SCALE;
                    float t0 = s0 + de_sh[rpA & 127] + pe_sh[(((rpA >> 7) & 7) - moA) & 7];
                    float t1 = s1 + de_sh[(rpA >> 16) & 127] + pe_sh[(((rpA >> 23) & 7) - moA) & 7];
                    float t2 = s2 + de_sh[rpB & 127] + pe_sh[(((rpB >> 7) & 7) - moB) & 7];
                    float t3 = s3 + de_sh[(rpB >> 16) & 127] + pe_sh[(((rpB >> 23) & 7) - moB) & 7];
                    int xb = 8 * j + 2 * t;
                    float w0 = ((mA >> xb) & 1) ? 0.f : __expf(t0);
                    float w1 = ((mA >> (xb + 1)) & 1) ? 0.f : __expf(t1);
                    float w2 = ((mB >> xb) & 1) ? 0.f : __expf(t2);
                    float w3 = ((mB >> (xb + 1)) & 1) ? 0.f : __expf(t3);
                    lr[m][0] += w0 + w1;
                    lr[m][1] += w2 + w3;
                    wv[jl][0] = w0; wv[jl][1] = w1; wv[jl][2] = w2; wv[jl][3] = w3;
                }
                uint32_t pah[4], pal[4];
                pah[0] = split_pack(wv[0][0], wv[0][1], pal[0]);
                pah[1] = split_pack(wv[0][2], wv[0][3], pal[1]);
                pah[2] = split_pack(wv[1][0], wv[1][1], pal[2]);
                pah[3] = split_pack(wv[1][2], wv[1][3], pal[3]);
#pragma unroll
                for (int n = 0; n < 4; n++) {
                    uint32_t b0h = vsh[cc * 8 + t][n * 8 + g];
                    uint32_t b1h = vsh[cc * 8 + t + 4][n * 8 + g];
                    uint32_t b0l = vsl[cc * 8 + t][n * 8 + g];
                    uint32_t b1l = vsl[cc * 8 + t + 4][n * 8 + g];
                    mma_bf16(accd[m][n], pah, b0h, b1h);
                    mma_bf16(accd[m][n], pal, b0h, b1h);
                    mma_bf16(accd[m][n], pah, b0l, b1l);
                }
            }
        }
    }

    // ---- write partials (same format as before: (l, acc[32])) ----
#pragma unroll
    for (int m = 0; m < 2; m++) {
        int rA = warpk + m * 16 + g;
        int rB = rA + 8;
        float lA = lr[m][0];
        lA += __shfl_xor_sync(0xffffffffu, lA, 1);
        lA += __shfl_xor_sync(0xffffffffu, lA, 2);
        float lB = lr[m][1];
        lB += __shfl_xor_sync(0xffffffffu, lB, 1);
        lB += __shfl_xor_sync(0xffffffffu, lB, 2);
        float* ppA = &g_part[(((size_t)bh * NSPLIT + xc) * KL + rA) * 33];
        float* ppB = &g_part[(((size_t)bh * NSPLIT + xc) * KL + rB) * 33];
        if (t == 0) { ppA[0] = lA; ppB[0] = lB; }
#pragma unroll
        for (int n = 0; n < 4; n++) {
            ppA[1 + n * 8 + 2 * t] = accd[m][n][0];
            ppA[2 + n * 8 + 2 * t] = accd[m][n][1];
            ppB[1 + n * 8 + 2 * t] = accd[m][n][2];
            ppB[2 + n * 8 + 2 * t] = accd[m][n][3];
        }
    }
}

// ---------------- K3c: combine x-splits -> preK (bf16 hi/lo out) ----------
__global__ void k3_combine()
{
    int idx = blockIdx.x * blockDim.x + threadIdx.x;
    if (idx >= B_ * H_ * KL * 16) return;
    int d2 = idx & 15;
    int k = (idx >> 4) & (KL - 1);
    int bh = idx >> 11;
    int h = bh % H_, b = bh / H_;
    const float* base = &g_part[((size_t)bh * NSPLIT) * KL * 33 + (size_t)k * 33];
    float L = 0.f, A0 = 0.f, A1 = 0.f;
    const size_t SSTR = (size_t)KL * 33;
#pragma unroll 8
    for (int s = 0; s < NSPLIT; s++) {
        L  += base[s * SSTR];
        A0 += base[s * SSTR + 1 + 2 * d2];
        A1 += base[s * SSTR + 2 + 2 * d2];
    }
    float invL = 1.f / L;
    uint32_t lo, hi = split_pack(A0 * invL, A1 * invL, lo);
    size_t o = ((size_t)b * KL + k) * (DIM / 2) + h * (HD / 2) + d2;
    g_pKh[o] = hi;
    g_pKl[o] = lo;
}

// ---------------- K4: x->kernel attention (2 x cols per thread) -----------
__global__ __launch_bounds__(128) void k4_xattn(
    const float* __restrict__ dis_embed, const float* __restrict__ polar_emb)
{
    __shared__ float kk_sh[KL * HD];
    __shared__ float kv_sh[KL * HD];
    __shared__ uint32_t mb_sh[KL][8];
    __shared__ float de_sh[NDIS];
    __shared__ float pe_sh[8];
    __shared__ int   mo_sh[KL];
    int tid = threadIdx.x;
    int xc = blockIdx.x, h = blockIdx.y, b = blockIdx.z;
    int bh = b * H_ + h;

    for (int g = tid; g < KL * HD / 4; g += 128) {
        int row = g >> 3, c4 = g & 7;
        ((float4*)kk_sh)[g] =
            *(const float4*)&g_QKVk[((size_t)(b * KL + row)) * TDIM + DIM + h * HD + c4 * 4];
        ((float4*)kv_sh)[g] =
            *(const float4*)&g_QKVk[((size_t)(b * KL + row)) * TDIM + 2 * DIM + h * HD + c4 * 4];
    }
    for (int g = tid; g < 256; g += 128) {
        int row = g >> 1, half = g & 1;
        *(uint4*)&mb_sh[row][half * 4] =
            *(const uint4*)&g_mb[((size_t)bh * KL + row) * (XL / 8) + xc * 32 + half * 16];
    }
    if (tid < NDIS) de_sh[tid] = dis_embed[tid * H_ + h];
    if (tid < 8) pe_sh[tid] = polar_emb[tid];
    if (tid < KL) mo_sh[tid] = g_mo[bh * KL + tid];
    __syncthreads();

    int xA = xc * 256 + tid;
    int xB = xA + 128;
    int wsel = tid >> 5, bsel = tid & 31;
    uint64_t qA[16], qB[16];
    {
        const uint64_t* pa = (const uint64_t*)&g_QKVx[((size_t)(b * XL + xA)) * TDIM + h * HD];
        const uint64_t* pb = (const uint64_t*)&g_QKVx[((size_t)(b * XL + xB)) * TDIM + h * HD];
#pragma unroll
        for (int i = 0; i < 16; i++) { qA[i] = pa[i]; qB[i] = pb[i]; }
    }
    const unsigned short* rpA = &g_rp[(size_t)b * KL * XL + xA];

    float lA = 0.f, lB = 0.f;
    uint64_t accA[16], accB[16];
#pragma unroll
    for (int d = 0; d < 16; d++) { accA[d] = 0; accB[d] = 0; }

    for (int kidx = 0; kidx < KL; kidx++) {
        const ulonglong2* kkp = (const ulonglong2*)&kk_sh[kidx * HD];
        uint64_t sa = 0, sb = 0;
#pragma unroll
        for (int d = 0; d < 8; d++) {
            ulonglong2 v = kkp[d];
            fma2(sa, qA[2 * d], v.x);
            fma2(sa, qA[2 * d + 1], v.y);
            fma2(sb, qB[2 * d], v.x);
            fma2(sb, qB[2 * d + 1], v.y);
        }
        float a0, a1, b0, b1;
        upk2(a0, a1, sa);
        upk2(b0, b1, sb);
        unsigned short pA = rpA[(size_t)kidx * XL];
        unsigned short pB = rpA[(size_t)kidx * XL + 128];
        int mo = mo_sh[kidx];
        float tA = (a0 + a1) * SCALE + de_sh[pA & 127] + pe_sh[(((pA >> 7) & 7) - mo) & 7];
        float tB = (b0 + b1) * SCALE + de_sh[pB & 127] + pe_sh[(((pB >> 7) & 7) - mo) & 7];
        float wA = ((mb_sh[kidx][wsel] >> bsel) & 1u) ? 0.f : __expf(tA);
        float wB = ((mb_sh[kidx][4 + wsel] >> bsel) & 1u) ? 0.f : __expf(tB);
        lA += wA;
        lB += wB;
        uint64_t wpA = pk2(wA, wA), wpB = pk2(wB, wB);
        const ulonglong2* vp = (const ulonglong2*)&kv_sh[kidx * HD];
#pragma unroll
        for (int d = 0; d < 8; d++) {
            ulonglong2 v = vp[d];
            fma2(accA[2 * d], wpA, v.x);
            fma2(accA[2 * d + 1], wpA, v.y);
            fma2(accB[2 * d], wpB, v.x);
            fma2(accB[2 * d + 1], wpB, v.y);
        }
    }
    float invA = 1.f / lA, invB = 1.f / lB;
    size_t obA = ((size_t)(b * XL + xA)) * (DIM / 2) + h * (HD / 2);
    size_t obB = ((size_t)(b * XL + xB)) * (DIM / 2) + h * (HD / 2);
#pragma unroll
    for (int d2 = 0; d2 < 16; d2++) {
        float a0, a1, b0, b1;
        upk2(a0, a1, accA[d2]);
        upk2(b0, b1, accB[d2]);
        uint32_t loA, hiA = split_pack(a0 * invA, a1 * invA, loA);
        uint32_t loB, hiB = split_pack(b0 * invB, b1 * invB, loB);
        g_pXh[obA + d2] = hiA; g_pXl[obA + d2] = loA;
        g_pXh[obB + d2] = hiB; g_pXl[obB + d2] = loB;
    }
}

// ---------------- host launcher ----------------
extern "C" void kernel_launch(void* const* d_in, const int* in_sizes, int n_in,
                              void* d_out, int out_size)
{
    const float* x     = (const float*)d_in[0];
    const float* kern  = (const float*)d_in[1];
    const int*   rd    = (const int*)d_in[2];
    const int*   polar = (const int*)d_in[3];
    const void*  mask  = d_in[4];
    const float* Wqkv  = (const float*)d_in[5];
    const float* dis   = (const float*)d_in[6];
    const float* pemb  = (const float*)d_in[7];
    const float* Wproj = (const float*)d_in[8];
    const float* bproj = (const float*)d_in[9];
    float* out = (float*)d_out;

    float* pQKVx; cudaGetSymbolAddress((void**)&pQKVx, g_QKVx);
    float* pQKVk; cudaGetSymbolAddress((void**)&pQKVk, g_QKVk);
    uint32_t *pxh, *pxl, *pkh, *pkl, *pwqh, *pwql, *pwph, *pwpl, *pXh, *pXl, *pKh, *pKl;
    cudaGetSymbolAddress((void**)&pxh, g_xhi);  cudaGetSymbolAddress((void**)&pxl, g_xlo);
    cudaGetSymbolAddress((void**)&pkh, g_khi);  cudaGetSymbolAddress((void**)&pkl, g_klo);
    cudaGetSymbolAddress((void**)&pwqh, g_wqh); cudaGetSymbolAddress((void**)&pwql, g_wql);
    cudaGetSymbolAddress((void**)&pwph, g_wph); cudaGetSymbolAddress((void**)&pwpl, g_wpl);
    cudaGetSymbolAddress((void**)&pXh, g_pXh);  cudaGetSymbolAddress((void**)&pXl, g_pXl);
    cudaGetSymbolAddress((void**)&pKh, g_pKh);  cudaGetSymbolAddress((void**)&pKl, g_pKl);

    // mask dtype probe + compact bias/mask tables
    det_reset<<<1, 32>>>();
    det_scan<<<256, 256>>>((const unsigned*)mask);
    rp16<<<(B_ * KL * XL / 2 + 255) / 256, 256>>>(rd, polar);
    maskbit<<<dim3(XL / 64, KL / 32, B_), dim3(32, 8)>>>(mask);

    // pre-split GEMM operands
    presplitA<<<(B_ * XL * DIM / 2 + 255) / 256, 256>>>(x, pxh, pxl, B_ * XL * DIM / 2);
    presplitA<<<(B_ * KL * DIM / 2 + 255) / 256, 256>>>(kern, pkh, pkl, B_ * KL * DIM / 2);
    presplitB<<<((DIM / 2) * TDIM + 255) / 256, 256>>>(Wqkv, pwqh, pwql, TDIM, (DIM / 2) * TDIM);
    presplitB<<<((DIM / 2) * DIM + 255) / 256, 256>>>(Wproj, pwph, pwpl, DIM, (DIM / 2) * DIM);

    // QKV projections
    gemm_pre<<<dim3(TDIM / 128, (B_ * XL) / 128), 256>>>(pxh, pxl, pwqh, pwql, nullptr, pQKVx, B_ * XL, TDIM, DIM);
    gemm_pre<<<dim3(TDIM / 128, (B_ * KL) / 128), 256>>>(pkh, pkl, pwqh, pwql, nullptr, pQKVk, B_ * KL, TDIM, DIM);

    // k3-mma operand prep
    prep_kq<<<(B_ * H_ * KL * 16 + 255) / 256, 256>>>();
    prep_kxv<<<dim3(XL / 64, H_, B_), 128>>>();

    // orientation bins + argmax
    k2_scores<<<dim3(NSPLIT, H_, B_), 64>>>();
    k2_argmax<<<(B_ * H_ * KL + 255) / 256, 256>>>();

    // kernel->x attention (tensor cores)
    k3_mma<<<dim3(NSPLIT, H_, B_), 128>>>(dis, pemb);
    k3_combine<<<(B_ * H_ * KL * 16 + 255) / 256, 256>>>();

    // x->kernel attention
    k4_xattn<<<dim3(XL / 256, H_, B_), 128>>>(dis, pemb);

    // output projections
    gemm_pre<<<dim3(DIM / 128, (B_ * XL) / 128), 256>>>(pXh, pXl, pwph, pwpl, bproj, out, B_ * XL, DIM, DIM);
    gemm_pre<<<dim3(DIM / 128, (B_ * KL) / 128), 256>>>(pKh, pKl, pwph, pwpl, bproj, out + (size_t)B_ * XL * DIM, B_ * KL, DIM, DIM);
}

// round 16
// speedup vs baseline: 1.2722x; 1.0998x over previous
#include <cuda_runtime.h>
#include <cuda_bf16.h>
#include <cstdint>

#define B_    4
#define KL    128
#define XL    4096
#define DIM   256
#define H_    8
#define HD    32
#define PB    8
#define NDIS  66
#define TDIM  768           // 3*DIM
#define SCALE 0.17677669529663687f
#define NSPLIT 32           // x-splits for k2/k3

// ---------------- scratch (device globals) ----------------
__device__ float    g_QKVx[B_ * XL * TDIM];
__device__ float    g_QKVk[B_ * KL * TDIM];
__device__ unsigned short g_rp[(size_t)B_ * KL * XL];          // rd | polar<<7 (4 MB)
__device__ uint8_t  g_mb[(size_t)B_ * H_ * KL * (XL / 8)];     // transposed mask bits (2 MB)
__device__ float    g_oriP[NSPLIT * B_ * H_ * KL * PB];
__device__ int      g_mo[B_ * H_ * KL];
__device__ float    g_part[(size_t)B_ * H_ * NSPLIT * KL * 33];
__device__ unsigned g_flags;
// pre-split bf16 hi/lo operand storage (u32 = packed bf16x2)
__device__ uint32_t g_xhi[B_ * XL * DIM / 2],  g_xlo[B_ * XL * DIM / 2];
__device__ uint32_t g_khi[B_ * KL * DIM / 2],  g_klo[B_ * KL * DIM / 2];
__device__ uint32_t g_wqh[(DIM / 2) * TDIM],   g_wql[(DIM / 2) * TDIM];
__device__ uint32_t g_wph[(DIM / 2) * DIM],    g_wpl[(DIM / 2) * DIM];
__device__ uint32_t g_pXh[B_ * XL * DIM / 2],  g_pXl[B_ * XL * DIM / 2];
__device__ uint32_t g_pKh[B_ * KL * DIM / 2],  g_pKl[B_ * KL * DIM / 2];
// k3-mma operands
__device__ uint32_t g_kqh[B_ * H_ * KL * 16],  g_kql[B_ * H_ * KL * 16];   // [bh][k][dpair]
__device__ uint32_t g_kxh2[(size_t)B_ * H_ * 16 * XL], g_kxl2[(size_t)B_ * H_ * 16 * XL]; // [bh][dpair][x]
__device__ uint32_t g_vxh[(size_t)B_ * H_ * (XL / 2) * 32], g_vxl[(size_t)B_ * H_ * (XL / 2) * 32]; // [bh][xpair][d]
// k4-mma operands
__device__ uint32_t g_qxh[(size_t)B_ * H_ * XL * 16], g_qxl[(size_t)B_ * H_ * XL * 16];   // [bh][x][dpair]

// ---------------- f32x2 packed helpers ----------------
__device__ __forceinline__ uint64_t pk2(float lo, float hi)
{
    uint64_t r;
    asm("mov.b64 %0, {%1, %2};" : "=l"(r) : "f"(lo), "f"(hi));
    return r;
}
__device__ __forceinline__ void upk2(float& lo, float& hi, uint64_t v)
{
    asm("mov.b64 {%0, %1}, %2;" : "=f"(lo), "=f"(hi) : "l"(v));
}
__device__ __forceinline__ void fma2(uint64_t& d, uint64_t a, uint64_t b)
{
    asm("fma.rn.f32x2 %0, %1, %2, %0;" : "+l"(d) : "l"(a), "l"(b));
}

// ---------------- bf16 split helper ----------------
__device__ __forceinline__ uint32_t split_pack(float x0, float x1, uint32_t& lo_pack)
{
    __nv_bfloat16 h0 = __float2bfloat16(x0);
    __nv_bfloat16 h1 = __float2bfloat16(x1);
    float l0 = x0 - __bfloat162float(h0);
    float l1 = x1 - __bfloat162float(h1);
    __nv_bfloat162 hp = __halves2bfloat162(h0, h1);
    __nv_bfloat162 lp = __halves2bfloat162(__float2bfloat16(l0), __float2bfloat16(l1));
    lo_pack = *(uint32_t*)&lp;
    return *(uint32_t*)&hp;
}

// ---------------- mask dtype probe ----------------
__global__ void det_reset() { if (threadIdx.x == 0) g_flags = 0u; }

__global__ void det_scan(const unsigned* __restrict__ w)
{
    int i = blockIdx.x * blockDim.x + threadIdx.x;
    unsigned v = w[i];
    unsigned f = 0;
    if (v == 0x3F800000u) f |= 1u;
    else if (v != 0u && v != 1u) f |= 2u;
    for (int o = 16; o > 0; o >>= 1) f |= __shfl_xor_sync(0xffffffffu, f, o);
    if ((threadIdx.x & 31) == 0 && f) atomicOr(&g_flags, f);
}

// ---------------- rp16 ----------------
__global__ void rp16(const int* __restrict__ rd, const int* __restrict__ polar)
{
    int i = blockIdx.x * blockDim.x + threadIdx.x;
    if (i >= B_ * KL * XL / 2) return;
    int2 r = *(const int2*)&rd[2 * i];
    int2 p = *(const int2*)&polar[2 * i];
    unsigned lo = (unsigned)(r.x | (p.x << 7));
    unsigned hi = (unsigned)(r.y | (p.y << 7));
    ((unsigned*)g_rp)[i] = lo | (hi << 16);
}

// ---------------- maskbit ----------------
__global__ void maskbit(const void* __restrict__ mask)
{
    __shared__ uint8_t m_sh[64][36];
    unsigned flags = g_flags;
    int mode = (flags & 1u) ? 2 : ((flags & 2u) ? 0 : 1);
    int x0 = blockIdx.x * 64, k0 = blockIdx.y * 32, b = blockIdx.z;
    int tx = threadIdx.x, ty = threadIdx.y;
    int tid = ty * 32 + tx;
    int ki = tid >> 3, jb = tid & 7;

    for (int h = 0; h < H_; h++) {
        size_t mb = ((size_t)((b * H_ + h)) * XL + x0) * KL + k0;
#pragma unroll
        for (int xi = ty; xi < 64; xi += 8) {
            uint8_t v;
            if (mode == 1)      v = ((const int*)mask)[mb + (size_t)xi * KL + tx] != 0;
            else if (mode == 2) v = ((const float*)mask)[mb + (size_t)xi * KL + tx] != 0.f;
            else                v = ((const uint8_t*)mask)[mb + (size_t)xi * KL + tx] != 0;
            m_sh[xi][tx] = v;
        }
        __syncthreads();
        uint8_t byte = 0;
#pragma unroll
        for (int i = 0; i < 8; i++)
            byte |= (uint8_t)(m_sh[8 * jb + i][ki] << i);
        g_mb[((size_t)((b * H_ + h) * KL + k0 + ki)) * (XL / 8) + (x0 >> 3) + jb] = byte;
        __syncthreads();
    }
}

// ---------------- presplit kernels (GEMM operands) ----------------
__global__ void presplitA(const float* __restrict__ A,
                          uint32_t* __restrict__ hi, uint32_t* __restrict__ lo, int n)
{
    int i = blockIdx.x * blockDim.x + threadIdx.x;
    if (i >= n) return;
    float2 v = *(const float2*)&A[2 * i];
    uint32_t l, h = split_pack(v.x, v.y, l);
    hi[i] = h; lo[i] = l;
}

__global__ void presplitB(const float* __restrict__ Bm,
                          uint32_t* __restrict__ hi, uint32_t* __restrict__ lo, int N, int n)
{
    int i = blockIdx.x * blockDim.x + threadIdx.x;
    if (i >= n) return;
    int p = i / N, c = i - p * N;
    uint32_t l, h = split_pack(Bm[(size_t)(2 * p) * N + c], Bm[(size_t)(2 * p + 1) * N + c], l);
    hi[i] = h; lo[i] = l;
}

// ---------------- prep for k3-mma ----------------
__global__ void prep_kq()
{
    int i = blockIdx.x * blockDim.x + threadIdx.x;
    if (i >= B_ * H_ * KL * 16) return;
    int dp = i & 15;
    int k = (i >> 4) & (KL - 1);
    int bh = i >> 11;
    int b = bh >> 3, h = bh & 7;
    const float* src = &g_QKVk[((size_t)(b * KL + k)) * TDIM + h * HD + 2 * dp];
    uint32_t l, hh = split_pack(src[0], src[1], l);
    g_kqh[i] = hh;
    g_kql[i] = l;
}

__global__ __launch_bounds__(128) void prep_kxv()
{
    __shared__ float kx_sh[64][33];
    __shared__ float v_sh[64][33];
    int tid = threadIdx.x;
    int xt = blockIdx.x, h = blockIdx.y, b = blockIdx.z;
    int bh = b * H_ + h;
    int x0 = xt * 64;

    for (int g = tid; g < 512; g += 128) {
        int row = g >> 3, c4 = g & 7;
        size_t rb = ((size_t)(b * XL + x0 + row)) * TDIM + h * HD + c4 * 4;
        float4 a = *(const float4*)&g_QKVx[rb + DIM];
        float4 v = *(const float4*)&g_QKVx[rb + 2 * DIM];
        kx_sh[row][c4 * 4 + 0] = a.x; kx_sh[row][c4 * 4 + 1] = a.y;
        kx_sh[row][c4 * 4 + 2] = a.z; kx_sh[row][c4 * 4 + 3] = a.w;
        v_sh[row][c4 * 4 + 0] = v.x;  v_sh[row][c4 * 4 + 1] = v.y;
        v_sh[row][c4 * 4 + 2] = v.z;  v_sh[row][c4 * 4 + 3] = v.w;
    }
    __syncthreads();
#pragma unroll
    for (int i = 0; i < 8; i++) {
        int e = tid + 128 * i;
        int dp = e >> 6, xx = e & 63;
        uint32_t l, hh = split_pack(kx_sh[xx][2 * dp], kx_sh[xx][2 * dp + 1], l);
        size_t o = ((size_t)bh * 16 + dp) * XL + x0 + xx;
        g_kxh2[o] = hh;
        g_kxl2[o] = l;
    }
#pragma unroll
    for (int i = 0; i < 8; i++) {
        int e = tid + 128 * i;
        int xp = e >> 5, d = e & 31;
        uint32_t l, hh = split_pack(v_sh[2 * xp][d], v_sh[2 * xp + 1][d], l);
        size_t o = ((size_t)bh * (XL / 2) + (x0 >> 1) + xp) * 32 + d;
        g_vxh[o] = hh;
        g_vxl[o] = l;
    }
}

// ---------------- prep for k4-mma: Q [bh][x][dpair] ----------------
__global__ void prep_qx()
{
    int i = blockIdx.x * blockDim.x + threadIdx.x;
    if (i >= B_ * H_ * XL * 16) return;
    int dp = i & 15;
    int x = (i >> 4) & (XL - 1);
    int bh = i >> 16;
    int b = bh >> 3, h = bh & 7;
    const float* src = &g_QKVx[((size_t)(b * XL + x)) * TDIM + h * HD + 2 * dp];
    uint32_t l, hh = split_pack(src[0], src[1], l);
    g_qxh[i] = hh;
    g_qxl[i] = l;
}

// ---------------- bf16x3 GEMM ----------------
__device__ __forceinline__ void mma_bf16(float* c, const uint32_t* a, uint32_t b0, uint32_t b1)
{
    asm("mma.sync.aligned.m16n8k16.row.col.f32.bf16.bf16.f32 "
        "{%0,%1,%2,%3}, {%4,%5,%6,%7}, {%8,%9}, {%0,%1,%2,%3};"
        : "+f"(c[0]), "+f"(c[1]), "+f"(c[2]), "+f"(c[3])
        : "r"(a[0]), "r"(a[1]), "r"(a[2]), "r"(a[3]), "r"(b0), "r"(b1));
}

__global__ __launch_bounds__(256, 2) void gemm_pre(
    const uint32_t* __restrict__ Ahi, const uint32_t* __restrict__ Alo,
    const uint32_t* __restrict__ Bhi, const uint32_t* __restrict__ Blo,
    const float* __restrict__ bias, float* __restrict__ C,
    int M, int N, int K)
{
    __shared__ uint32_t AsH[128][20];
    __shared__ uint32_t AsL[128][20];
    __shared__ uint32_t BsH[16][136];
    __shared__ uint32_t BsL[16][136];
    int tid = threadIdx.x;
    int wid = tid >> 5, lane = tid & 31;
    int g = lane >> 2, t = lane & 3;
    int wm = wid & 1, wn = wid >> 1;
    int cCol = blockIdx.x, cRow = blockIdx.y;
    const int KP = K >> 1;

    float acc[4][4][4];
#pragma unroll
    for (int i = 0; i < 4; i++)
#pragma unroll
        for (int j = 0; j < 4; j++)
#pragma unroll
            for (int c = 0; c < 4; c++) acc[i][j][c] = 0.f;

    for (int k0p = 0; k0p < KP; k0p += 16) {
#pragma unroll
        for (int j = 0; j < 4; j++) {
            int f = tid + 256 * j;
            int r = f >> 3, p2 = (f & 7) * 2;
            size_t off = (size_t)(cRow * 128 + r) * KP + k0p + p2;
            uint2 h = *(const uint2*)&Ahi[off];
            uint2 l = *(const uint2*)&Alo[off];
            AsH[r][p2] = h.x; AsH[r][p2 + 1] = h.y;
            AsL[r][p2] = l.x; AsL[r][p2 + 1] = l.y;
        }
#pragma unroll
        for (int j = 0; j < 4; j++) {
            int f = tid + 256 * j;
            int pr = f >> 6, c2 = (f & 63) * 2;
            size_t off = (size_t)(k0p + pr) * N + cCol * 128 + c2;
            uint2 h = *(const uint2*)&Bhi[off];
            uint2 l = *(const uint2*)&Blo[off];
            BsH[pr][c2] = h.x; BsH[pr][c2 + 1] = h.y;
            BsL[pr][c2] = l.x; BsL[pr][c2 + 1] = l.y;
        }
        __syncthreads();

#pragma unroll
        for (int kk = 0; kk < 2; kk++) {
            uint32_t ah[4][4], al[4][4];
#pragma unroll
            for (int mi = 0; mi < 4; mi++) {
                int ar = wm * 64 + mi * 16 + g;
                int pc = kk * 8 + t;
                ah[mi][0] = AsH[ar][pc];         al[mi][0] = AsL[ar][pc];
                ah[mi][1] = AsH[ar + 8][pc];     al[mi][1] = AsL[ar + 8][pc];
                ah[mi][2] = AsH[ar][pc + 4];     al[mi][2] = AsL[ar][pc + 4];
                ah[mi][3] = AsH[ar + 8][pc + 4]; al[mi][3] = AsL[ar + 8][pc + 4];
            }
#pragma unroll
            for (int ni = 0; ni < 4; ni++) {
                int bc = wn * 32 + ni * 8 + g;
                int pr = kk * 8 + t;
                uint32_t bh0 = BsH[pr][bc], bh1 = BsH[pr + 4][bc];
                uint32_t bl0 = BsL[pr][bc], bl1 = BsL[pr + 4][bc];
#pragma unroll
                for (int mi = 0; mi < 4; mi++) {
                    mma_bf16(acc[mi][ni], ah[mi], bh0, bh1);
                    mma_bf16(acc[mi][ni], al[mi], bh0, bh1);
                    mma_bf16(acc[mi][ni], ah[mi], bl0, bl1);
                }
            }
        }
        __syncthreads();
    }

#pragma unroll
    for (int mi = 0; mi < 4; mi++) {
#pragma unroll
        for (int ni = 0; ni < 4; ni++) {
            int r0 = cRow * 128 + wm * 64 + mi * 16 + g;
            int c0 = cCol * 128 + wn * 32 + ni * 8 + 2 * t;
            float b0 = bias ? bias[c0] : 0.f;
            float b1 = bias ? bias[c0 + 1] : 0.f;
            float2 v01 = make_float2(acc[mi][ni][0] + b0, acc[mi][ni][1] + b1);
            float2 v23 = make_float2(acc[mi][ni][2] + b0, acc[mi][ni][3] + b1);
            *(float2*)&C[(size_t)r0 * N + c0] = v01;
            *(float2*)&C[(size_t)(r0 + 8) * N + c0] = v23;
        }
    }
}

// ---------------- K2: orientation bins (2 k rows per thread) --------------
__global__ __launch_bounds__(64) void k2_scores()
{
    int t = threadIdx.x;
    int xc = blockIdx.x, h = blockIdx.y, b = blockIdx.z;
    int bh = b * H_ + h;
    int xbase = xc * (XL / NSPLIT);
    __shared__ float kx_sh[64 * 32];
    __shared__ unsigned pk_sh[128 * 33];

    uint64_t kqa[16], kqb[16];
    {
        const uint64_t* pa = (const uint64_t*)&g_QKVk[((size_t)(b * KL + t)) * TDIM + h * HD];
        const uint64_t* pb = (const uint64_t*)&g_QKVk[((size_t)(b * KL + t + 64)) * TDIM + h * HD];
#pragma unroll
        for (int i = 0; i < 16; i++) { kqa[i] = pa[i]; kqb[i] = pb[i]; }
    }

    float binsA[8], binsB[8];
#pragma unroll
    for (int o = 0; o < 8; o++) { binsA[o] = 0.f; binsB[o] = 0.f; }

    const unsigned* pkg = (const unsigned*)&g_rp[(size_t)b * KL * XL];

    for (int c = 0; c < 2; c++) {
        int xs = xbase + c * 64;
        __syncthreads();
        for (int g = t; g < 512; g += 64) {
            int row = g >> 3, c4 = g & 7;
            ((float4*)kx_sh)[g] =
                *(const float4*)&g_QKVx[((size_t)(b * XL + xs + row)) * TDIM + DIM + h * HD + c4 * 4];
        }
        for (int g = t; g < 1024; g += 64) {
            int row = g >> 3, q = g & 7;
            uint4 v = *(const uint4*)&pkg[(size_t)row * (XL / 2) + (xs >> 1) + q * 4];
            pk_sh[row * 33 + q * 4 + 0] = v.x;
            pk_sh[row * 33 + q * 4 + 1] = v.y;
            pk_sh[row * 33 + q * 4 + 2] = v.z;
            pk_sh[row * 33 + q * 4 + 3] = v.w;
        }
        __syncthreads();
        const unsigned short* prA = (const unsigned short*)&pk_sh[t * 33];
        const unsigned short* prB = (const unsigned short*)&pk_sh[(t + 64) * 33];
        for (int j = 0; j < 64; j++) {
            const ulonglong2* kx2 = (const ulonglong2*)&kx_sh[j * 32];
            uint64_t sa = 0, sb = 0;
#pragma unroll
            for (int d = 0; d < 8; d++) {
                ulonglong2 v = kx2[d];
                fma2(sa, kqa[2 * d], v.x);
                fma2(sa, kqa[2 * d + 1], v.y);
                fma2(sb, kqb[2 * d], v.x);
                fma2(sb, kqb[2 * d + 1], v.y);
            }
            float a0, a1, b0, b1;
            upk2(a0, a1, sa);
            upk2(b0, b1, sb);
            float asA = fabsf((a0 + a1) * SCALE);
            float asB = fabsf((b0 + b1) * SCALE);
            int pvA = (prA[j] >> 7) & 7;
            int pvB = (prB[j] >> 7) & 7;
#pragma unroll
            for (int o = 0; o < 8; o++) {
                binsA[o] += (pvA == o) ? asA : 0.f;
                binsB[o] += (pvB == o) ? asB : 0.f;
            }
        }
    }
    float* oA = &g_oriP[((size_t)xc * B_ * H_ * KL + bh * KL + t) * 8];
    float* oB = &g_oriP[((size_t)xc * B_ * H_ * KL + bh * KL + t + 64) * 8];
#pragma unroll
    for (int o = 0; o < 8; o++) { oA[o] = binsA[o]; oB[o] = binsB[o]; }
}

// ---------------- K2c ----------------
__global__ void k2_argmax()
{
    int idx = blockIdx.x * blockDim.x + threadIdx.x;
    if (idx >= B_ * H_ * KL) return;
    float s[8];
#pragma unroll
    for (int o = 0; o < 8; o++) s[o] = 0.f;
    for (int xc = 0; xc < NSPLIT; xc++) {
        const float* p = &g_oriP[((size_t)xc * B_ * H_ * KL + idx) * 8];
#pragma unroll
        for (int o = 0; o < 8; o++) s[o] += p[o];
    }
    int best = 0;
    float bv = s[0];
#pragma unroll
    for (int p = 1; p < 8; p++)
        if (s[p] > bv) { bv = s[p]; best = p; }
    g_mo[idx] = best;
}

// ---------------- K3-MMA (proven round-15 kernel, unchanged) --------------
__global__ __launch_bounds__(128) void k3_mma(
    const float* __restrict__ dis_embed, const float* __restrict__ polar_emb)
{
    __shared__ uint32_t bxh[16][72], bxl[16][72];
    __shared__ uint32_t vsh[32][40], vsl[32][40];
    __shared__ uint32_t rp_sh[128 * 33];
    __shared__ uint64_t mb_sh[128];
    __shared__ float de_sh[NDIS];
    __shared__ float pe_sh[8];

    int tid = threadIdx.x;
    int wid = tid >> 5, lane = tid & 31;
    int g = lane >> 2, t = lane & 3;
    int xc = blockIdx.x, h = blockIdx.y, b = blockIdx.z;
    int bh = b * H_ + h;
    int warpk = wid * 32;

    if (tid < NDIS) de_sh[tid] = dis_embed[tid * H_ + h];
    if (tid < 8) pe_sh[tid] = polar_emb[tid];

    uint32_t aqh[2][2][4], aql[2][2][4];
    int mov[2][2];
#pragma unroll
    for (int m = 0; m < 2; m++) {
        int rA = warpk + m * 16 + g;
        int rB = rA + 8;
#pragma unroll
        for (int c = 0; c < 2; c++) {
            size_t baseA = ((size_t)bh * KL + rA) * 16 + c * 8 + t;
            size_t baseB = ((size_t)bh * KL + rB) * 16 + c * 8 + t;
            aqh[m][c][0] = g_kqh[baseA];
            aqh[m][c][1] = g_kqh[baseB];
            aqh[m][c][2] = g_kqh[baseA + 4];
            aqh[m][c][3] = g_kqh[baseB + 4];
            aql[m][c][0] = g_kql[baseA];
            aql[m][c][1] = g_kql[baseB];
            aql[m][c][2] = g_kql[baseA + 4];
            aql[m][c][3] = g_kql[baseB + 4];
        }
        mov[m][0] = g_mo[bh * KL + rA];
        mov[m][1] = g_mo[bh * KL + rB];
    }

    float accd[2][4][4];
#pragma unroll
    for (int m = 0; m < 2; m++)
#pragma unroll
        for (int n = 0; n < 4; n++)
#pragma unroll
            for (int c = 0; c < 4; c++) accd[m][n][c] = 0.f;
    float lr[2][2] = {{0.f, 0.f}, {0.f, 0.f}};

    const unsigned* rp32 = (const unsigned*)g_rp;

    for (int xt = 0; xt < 2; xt++) {
        int x0 = xc * 128 + xt * 64;
        __syncthreads();
#pragma unroll
        for (int i = 0; i < 8; i++) {
            int e = tid + 128 * i;
            int dp = e >> 6, xx = e & 63;
            size_t o = ((size_t)bh * 16 + dp) * XL + x0 + xx;
            bxh[dp][xx] = g_kxh2[o];
            bxl[dp][xx] = g_kxl2[o];
        }
#pragma unroll
        for (int i = 0; i < 8; i++) {
            int e = tid + 128 * i;
            int xp = e >> 5, d = e & 31;
            size_t o = ((size_t)bh * (XL / 2) + (x0 >> 1) + xp) * 32 + d;
            vsh[xp][d] = g_vxh[o];
            vsl[xp][d] = g_vxl[o];
        }
#pragma unroll
        for (int i = 0; i < 32; i++) {
            int e = tid + 128 * i;
            int row = e >> 5, col = e & 31;
            rp_sh[row * 33 + col] = rp32[(size_t)(b * KL + row) * (XL / 2) + (x0 >> 1) + col];
        }
        mb_sh[tid] = *(const uint64_t*)&g_mb[((size_t)bh * KL + tid) * (XL / 8) + (x0 >> 3)];
        __syncthreads();

        float sf[2][8][4];
#pragma unroll
        for (int m = 0; m < 2; m++)
#pragma unroll
            for (int j = 0; j < 8; j++) {
                sf[m][j][0] = sf[m][j][1] = sf[m][j][2] = sf[m][j][3] = 0.f;
#pragma unroll
                for (int c = 0; c < 2; c++) {
                    uint32_t b0h = bxh[c * 8 + t][j * 8 + g];
                    uint32_t b1h = bxh[c * 8 + t + 4][j * 8 + g];
                    uint32_t b0l = bxl[c * 8 + t][j * 8 + g];
                    uint32_t b1l = bxl[c * 8 + t + 4][j * 8 + g];
                    mma_bf16(sf[m][j], aqh[m][c], b0h, b1h);
                    mma_bf16(sf[m][j], aql[m][c], b0h, b1h);
                    mma_bf16(sf[m][j], aqh[m][c], b0l, b1l);
                }
            }

#pragma unroll
        for (int m = 0; m < 2; m++) {
            int rA = warpk + m * 16 + g;
            int rB = rA + 8;
            uint64_t mA = mb_sh[rA];
            uint64_t mB = mb_sh[rB];
            int moA = mov[m][0], moB = mov[m][1];
#pragma unroll
            for (int cc = 0; cc < 4; cc++) {
                float wv[2][4];
#pragma unroll
                for (int jl = 0; jl < 2; jl++) {
                    int j = 2 * cc + jl;
                    unsigned rpA = rp_sh[rA * 33 + 4 * j + t];
                    unsigned rpB = rp_sh[rB * 33 + 4 * j + t];
                    float s0 = sf[m][j][0] * SCALE;
                    float s1 = sf[m][j][1] * SCALE;
                    float s2 = sf[m][j][2] * SCALE;
                    float s3 = sf[m][j][3] * SCALE;
                    float t0 = s0 + de_sh[rpA & 127] + pe_sh[(((rpA >> 7) & 7) - moA) & 7];
                    float t1 = s1 + de_sh[(rpA >> 16) & 127] + pe_sh[(((rpA >> 23) & 7) - moA) & 7];
                    float t2 = s2 + de_sh[rpB & 127] + pe_sh[(((rpB >> 7) & 7) - moB) & 7];
                    float t3 = s3 + de_sh[(rpB >> 16) & 127] + pe_sh[(((rpB >> 23) & 7) - moB) & 7];
                    int xb = 8 * j + 2 * t;
                    float w0 = ((mA >> xb) & 1) ? 0.f : __expf(t0);
                    float w1 = ((mA >> (xb + 1)) & 1) ? 0.f : __expf(t1);
                    float w2 = ((mB >> xb) & 1) ? 0.f : __expf(t2);
                    float w3 = ((mB >> (xb + 1)) & 1) ? 0.f : __expf(t3);
                    lr[m][0] += w0 + w1;
                    lr[m][1] += w2 + w3;
                    wv[jl][0] = w0; wv[jl][1] = w1; wv[jl][2] = w2; wv[jl][3] = w3;
                }
                uint32_t pah[4], pal[4];
                pah[0] = split_pack(wv[0][0], wv[0][1], pal[0]);
                pah[1] = split_pack(wv[0][2], wv[0][3], pal[1]);
                pah[2] = split_pack(wv[1][0], wv[1][1], pal[2]);
                pah[3] = split_pack(wv[1][2], wv[1][3], pal[3]);
#pragma unroll
                for (int n = 0; n < 4; n++) {
                    uint32_t b0h = vsh[cc * 8 + t][n * 8 + g];
                    uint32_t b1h = vsh[cc * 8 + t + 4][n * 8 + g];
                    uint32_t b0l = vsl[cc * 8 + t][n * 8 + g];
                    uint32_t b1l = vsl[cc * 8 + t + 4][n * 8 + g];
                    mma_bf16(accd[m][n], pah, b0h, b1h);
                    mma_bf16(accd[m][n], pal, b0h, b1h);
                    mma_bf16(accd[m][n], pah, b0l, b1l);
                }
            }
        }
    }

#pragma unroll
    for (int m = 0; m < 2; m++) {
        int rA = warpk + m * 16 + g;
        int rB = rA + 8;
        float lA = lr[m][0];
        lA += __shfl_xor_sync(0xffffffffu, lA, 1);
        lA += __shfl_xor_sync(0xffffffffu, lA, 2);
        float lB = lr[m][1];
        lB += __shfl_xor_sync(0xffffffffu, lB, 1);
        lB += __shfl_xor_sync(0xffffffffu, lB, 2);
        float* ppA = &g_part[(((size_t)bh * NSPLIT + xc) * KL + rA) * 33];
        float* ppB = &g_part[(((size_t)bh * NSPLIT + xc) * KL + rB) * 33];
        if (t == 0) { ppA[0] = lA; ppB[0] = lB; }
#pragma unroll
        for (int n = 0; n < 4; n++) {
            ppA[1 + n * 8 + 2 * t] = accd[m][n][0];
            ppA[2 + n * 8 + 2 * t] = accd[m][n][1];
            ppB[1 + n * 8 + 2 * t] = accd[m][n][2];
            ppB[2 + n * 8 + 2 * t] = accd[m][n][3];
        }
    }
}

// ---------------- K3c ----------------
__global__ void k3_combine()
{
    int idx = blockIdx.x * blockDim.x + threadIdx.x;
    if (idx >= B_ * H_ * KL * 16) return;
    int d2 = idx & 15;
    int k = (idx >> 4) & (KL - 1);
    int bh = idx >> 11;
    int h = bh % H_, b = bh / H_;
    const float* base = &g_part[((size_t)bh * NSPLIT) * KL * 33 + (size_t)k * 33];
    float L = 0.f, A0 = 0.f, A1 = 0.f;
    const size_t SSTR = (size_t)KL * 33;
#pragma unroll 8
    for (int s = 0; s < NSPLIT; s++) {
        L  += base[s * SSTR];
        A0 += base[s * SSTR + 1 + 2 * d2];
        A1 += base[s * SSTR + 2 + 2 * d2];
    }
    float invL = 1.f / L;
    uint32_t lo, hi = split_pack(A0 * invL, A1 * invL, lo);
    size_t o = ((size_t)b * KL + k) * (DIM / 2) + h * (HD / 2) + d2;
    g_pKh[o] = hi;
    g_pKl[o] = lo;
}

// ---------------- K4-MMA: x->kernel attention via tensor cores ------------
// grid (XL/128, H, B), block 128 (4 warps); warp w owns x rows [32w, 32w+32)
__global__ __launch_bounds__(128) void k4_mma(
    const float* __restrict__ dis_embed, const float* __restrict__ polar_emb)
{
    __shared__ uint32_t kkb_h[16][136], kkb_l[16][136];  // kk [dpair][k]
    __shared__ uint32_t kvb_h[64][40],  kvb_l[64][40];   // kv [kpair][d]
    __shared__ uint32_t mb_sh[128][4];                   // mask bits [k][x/32]
    __shared__ float de_sh[NDIS];
    __shared__ float pe_sh[8];
    __shared__ int   mo_sh[KL];

    int tid = threadIdx.x;
    int wid = tid >> 5, lane = tid & 31;
    int g = lane >> 2, t = lane & 3;
    int xc = blockIdx.x, h = blockIdx.y, b = blockIdx.z;
    int bh = b * H_ + h;
    int warpx = wid * 32;

    // stage kk (split in-kernel)
#pragma unroll
    for (int i = 0; i < 16; i++) {
        int e = tid + 128 * i;
        int k = e >> 4, dp = e & 15;
        float2 v = *(const float2*)&g_QKVk[((size_t)(b * KL + k)) * TDIM + DIM + h * HD + 2 * dp];
        uint32_t l, hh = split_pack(v.x, v.y, l);
        kkb_h[dp][k] = hh;
        kkb_l[dp][k] = l;
    }
    // stage kv
#pragma unroll
    for (int i = 0; i < 16; i++) {
        int e = tid + 128 * i;
        int kp = e >> 5, d = e & 31;
        float v0 = g_QKVk[((size_t)(b * KL + 2 * kp)) * TDIM + 2 * DIM + h * HD + d];
        float v1 = g_QKVk[((size_t)(b * KL + 2 * kp + 1)) * TDIM + 2 * DIM + h * HD + d];
        uint32_t l, hh = split_pack(v0, v1, l);
        kvb_h[kp][d] = hh;
        kvb_l[kp][d] = l;
    }
    *(uint4*)&mb_sh[tid][0] =
        *(const uint4*)&g_mb[((size_t)bh * KL + tid) * (XL / 8) + xc * 16];
    if (tid < NDIS) de_sh[tid] = dis_embed[tid * H_ + h];
    if (tid < 8) pe_sh[tid] = polar_emb[tid];
    mo_sh[tid] = g_mo[bh * KL + tid];
    __syncthreads();

    // A-frags: Q rows for this warp
    uint32_t aqh[2][2][4], aql[2][2][4];
#pragma unroll
    for (int m = 0; m < 2; m++) {
        int rA = xc * 128 + warpx + m * 16 + g;
        int rB = rA + 8;
#pragma unroll
        for (int c = 0; c < 2; c++) {
            size_t baseA = ((size_t)bh * XL + rA) * 16 + c * 8 + t;
            size_t baseB = ((size_t)bh * XL + rB) * 16 + c * 8 + t;
            aqh[m][c][0] = g_qxh[baseA];
            aqh[m][c][1] = g_qxh[baseB];
            aqh[m][c][2] = g_qxh[baseA + 4];
            aqh[m][c][3] = g_qxh[baseB + 4];
            aql[m][c][0] = g_qxl[baseA];
            aql[m][c][1] = g_qxl[baseB];
            aql[m][c][2] = g_qxl[baseA + 4];
            aql[m][c][3] = g_qxl[baseB + 4];
        }
    }

    float accd[2][4][4];
#pragma unroll
    for (int m = 0; m < 2; m++)
#pragma unroll
        for (int n = 0; n < 4; n++)
#pragma unroll
            for (int c = 0; c < 4; c++) accd[m][n][c] = 0.f;
    float lr[2][2] = {{0.f, 0.f}, {0.f, 0.f}};

    for (int kt = 0; kt < 2; kt++) {
        // mma1: scores for k cols [kt*64, kt*64+64)
        float sf[2][8][4];
#pragma unroll
        for (int m = 0; m < 2; m++)
#pragma unroll
            for (int j = 0; j < 8; j++) {
                sf[m][j][0] = sf[m][j][1] = sf[m][j][2] = sf[m][j][3] = 0.f;
#pragma unroll
                for (int c = 0; c < 2; c++) {
                    uint32_t b0h = kkb_h[c * 8 + t][kt * 64 + j * 8 + g];
                    uint32_t b1h = kkb_h[c * 8 + t + 4][kt * 64 + j * 8 + g];
                    uint32_t b0l = kkb_l[c * 8 + t][kt * 64 + j * 8 + g];
                    uint32_t b1l = kkb_l[c * 8 + t + 4][kt * 64 + j * 8 + g];
                    mma_bf16(sf[m][j], aqh[m][c], b0h, b1h);
                    mma_bf16(sf[m][j], aql[m][c], b0h, b1h);
                    mma_bf16(sf[m][j], aqh[m][c], b0l, b1l);
                }
            }

        // epilogue + mma2 over 16-k chunks within this half
#pragma unroll
        for (int m = 0; m < 2; m++) {
            int xbA = warpx + m * 16 + g;          // x bit index within block
            int xbB = xbA + 8;
            int xA = xc * 128 + xbA;
            int xB = xA + 8;
#pragma unroll
            for (int cc = 0; cc < 4; cc++) {
                float wv[2][4];
#pragma unroll
                for (int jl = 0; jl < 2; jl++) {
                    int j = 2 * cc + jl;
                    int kc0 = kt * 64 + j * 8 + 2 * t;
                    int kc1 = kc0 + 1;
                    unsigned short rp0A = g_rp[(size_t)(b * KL + kc0) * XL + xA];
                    unsigned short rp1A = g_rp[(size_t)(b * KL + kc1) * XL + xA];
                    unsigned short rp0B = g_rp[(size_t)(b * KL + kc0) * XL + xB];
                    unsigned short rp1B = g_rp[(size_t)(b * KL + kc1) * XL + xB];
                    int mo0 = mo_sh[kc0], mo1 = mo_sh[kc1];
                    float t0 = sf[m][j][0] * SCALE + de_sh[rp0A & 127] + pe_sh[(((rp0A >> 7) & 7) - mo0) & 7];
                    float t1 = sf[m][j][1] * SCALE + de_sh[rp1A & 127] + pe_sh[(((rp1A >> 7) & 7) - mo1) & 7];
                    float t2 = sf[m][j][2] * SCALE + de_sh[rp0B & 127] + pe_sh[(((rp0B >> 7) & 7) - mo0) & 7];
                    float t3 = sf[m][j][3] * SCALE + de_sh[rp1B & 127] + pe_sh[(((rp1B >> 7) & 7) - mo1) & 7];
                    float w0 = ((mb_sh[kc0][xbA >> 5] >> (xbA & 31)) & 1u) ? 0.f : __expf(t0);
                    float w1 = ((mb_sh[kc1][xbA >> 5] >> (xbA & 31)) & 1u) ? 0.f : __expf(t1);
                    float w2 = ((mb_sh[kc0][xbB >> 5] >> (xbB & 31)) & 1u) ? 0.f : __expf(t2);
                    float w3 = ((mb_sh[kc1][xbB >> 5] >> (xbB & 31)) & 1u) ? 0.f : __expf(t3);
                    lr[m][0] += w0 + w1;
                    lr[m][1] += w2 + w3;
                    wv[jl][0] = w0; wv[jl][1] = w1; wv[jl][2] = w2; wv[jl][3] = w3;
                }
                uint32_t pah[4], pal[4];
                pah[0] = split_pack(wv[0][0], wv[0][1], pal[0]);
                pah[1] = split_pack(wv[0][2], wv[0][3], pal[1]);
                pah[2] = split_pack(wv[1][0], wv[1][1], pal[2]);
                pah[3] = split_pack(wv[1][2], wv[1][3], pal[3]);
#pragma unroll
                for (int n = 0; n < 4; n++) {
                    uint32_t b0h = kvb_h[kt * 32 + cc * 8 + t][n * 8 + g];
                    uint32_t b1h = kvb_h[kt * 32 + cc * 8 + t + 4][n * 8 + g];
                    uint32_t b0l = kvb_l[kt * 32 + cc * 8 + t][n * 8 + g];
                    uint32_t b1l = kvb_l[kt * 32 + cc * 8 + t + 4][n * 8 + g];
                    mma_bf16(accd[m][n], pah, b0h, b1h);
                    mma_bf16(accd[m][n], pal, b0h, b1h);
                    mma_bf16(accd[m][n], pah, b0l, b1l);
                }
            }
        }
    }

    // normalize + write preX as bf16 hi/lo
#pragma unroll
    for (int m = 0; m < 2; m++) {
        int xA = xc * 128 + warpx + m * 16 + g;
        int xB = xA + 8;
        float lA = lr[m][0];
        lA += __shfl_xor_sync(0xffffffffu, lA, 1);
        lA += __shfl_xor_sync(0xffffffffu, lA, 2);
        float lB = lr[m][1];
        lB += __shfl_xor_sync(0xffffffffu, lB, 1);
        lB += __shfl_xor_sync(0xffffffffu, lB, 2);
        float invA = 1.f / lA, invB = 1.f / lB;
        size_t obA = ((size_t)(b * XL + xA)) * (DIM / 2) + h * (HD / 2);
        size_t obB = ((size_t)(b * XL + xB)) * (DIM / 2) + h * (HD / 2);
#pragma unroll
        for (int n = 0; n < 4; n++) {
            int dp = n * 4 + t;
            uint32_t loA, hiA = split_pack(accd[m][n][0] * invA, accd[m][n][1] * invA, loA);
            uint32_t loB, hiB = split_pack(accd[m][n][2] * invB, accd[m][n][3] * invB, loB);
            g_pXh[obA + dp] = hiA; g_pXl[obA + dp] = loA;
            g_pXh[obB + dp] = hiB; g_pXl[obB + dp] = loB;
        }
    }
}

// ---------------- host launcher ----------------
extern "C" void kernel_launch(void* const* d_in, const int* in_sizes, int n_in,
                              void* d_out, int out_size)
{
    const float* x     = (const float*)d_in[0];
    const float* kern  = (const float*)d_in[1];
    const int*   rd    = (const int*)d_in[2];
    const int*   polar = (const int*)d_in[3];
    const void*  mask  = d_in[4];
    const float* Wqkv  = (const float*)d_in[5];
    const float* dis   = (const float*)d_in[6];
    const float* pemb  = (const float*)d_in[7];
    const float* Wproj = (const float*)d_in[8];
    const float* bproj = (const float*)d_in[9];
    float* out = (float*)d_out;

    float* pQKVx; cudaGetSymbolAddress((void**)&pQKVx, g_QKVx);
    float* pQKVk; cudaGetSymbolAddress((void**)&pQKVk, g_QKVk);
    uint32_t *pxh, *pxl, *pkh, *pkl, *pwqh, *pwql, *pwph, *pwpl, *pXh, *pXl, *pKh, *pKl;
    cudaGetSymbolAddress((void**)&pxh, g_xhi);  cudaGetSymbolAddress((void**)&pxl, g_xlo);
    cudaGetSymbolAddress((void**)&pkh, g_khi);  cudaGetSymbolAddress((void**)&pkl, g_klo);
    cudaGetSymbolAddress((void**)&pwqh, g_wqh); cudaGetSymbolAddress((void**)&pwql, g_wql);
    cudaGetSymbolAddress((void**)&pwph, g_wph); cudaGetSymbolAddress((void**)&pwpl, g_wpl);
    cudaGetSymbolAddress((void**)&pXh, g_pXh);  cudaGetSymbolAddress((void**)&pXl, g_pXl);
    cudaGetSymbolAddress((void**)&pKh, g_pKh);  cudaGetSymbolAddress((void**)&pKl, g_pKl);

    // mask dtype probe + compact bias/mask tables
    det_reset<<<1, 32>>>();
    det_scan<<<256, 256>>>((const unsigned*)mask);
    rp16<<<(B_ * KL * XL / 2 + 255) / 256, 256>>>(rd, polar);
    maskbit<<<dim3(XL / 64, KL / 32, B_), dim3(32, 8)>>>(mask);

    // pre-split GEMM operands
    presplitA<<<(B_ * XL * DIM / 2 + 255) / 256, 256>>>(x, pxh, pxl, B_ * XL * DIM / 2);
    presplitA<<<(B_ * KL * DIM / 2 + 255) / 256, 256>>>(kern, pkh, pkl, B_ * KL * DIM / 2);
    presplitB<<<((DIM / 2) * TDIM + 255) / 256, 256>>>(Wqkv, pwqh, pwql, TDIM, (DIM / 2) * TDIM);
    presplitB<<<((DIM / 2) * DIM + 255) / 256, 256>>>(Wproj, pwph, pwpl, DIM, (DIM / 2) * DIM);

    // QKV projections
    gemm_pre<<<dim3(TDIM / 128, (B_ * XL) / 128), 256>>>(pxh, pxl, pwqh, pwql, nullptr, pQKVx, B_ * XL, TDIM, DIM);
    gemm_pre<<<dim3(TDIM / 128, (B_ * KL) / 128), 256>>>(pkh, pkl, pwqh, pwql, nullptr, pQKVk, B_ * KL, TDIM, DIM);

    // attention operand prep
    prep_kq<<<(B_ * H_ * KL * 16 + 255) / 256, 256>>>();
    prep_kxv<<<dim3(XL / 64, H_, B_), 128>>>();
    prep_qx<<<(B_ * H_ * XL * 16 + 255) / 256, 256>>>();

    // orientation bins + argmax
    k2_scores<<<dim3(NSPLIT, H_, B_), 64>>>();
    k2_argmax<<<(B_ * H_ * KL + 255) / 256, 256>>>();

    // kernel->x attention (tensor cores)
    k3_mma<<<dim3(NSPLIT, H_, B_), 128>>>(dis, pemb);
    k3_combine<<<(B_ * H_ * KL * 16 + 255) / 256, 256>>>();

    // x->kernel attention (tensor cores)
    k4_mma<<<dim3(XL / 128, H_, B_), 128>>>(dis, pemb);

    // output projections
    gemm_pre<<<dim3(DIM / 128, (B_ * XL) / 128), 256>>>(pXh, pXl, pwph, pwpl, bproj, out, B_ * XL, DIM, DIM);
    gemm_pre<<<dim3(DIM / 128, (B_ * KL) / 128), 256>>>(pKh, pKl, pwph, pwpl, bproj, out + (size_t)B_ * XL * DIM, B_ * KL, DIM, DIM);
}

// round 17
// speedup vs baseline: 1.4336x; 1.1268x over previous
#include <cuda_runtime.h>
#include <cuda_bf16.h>
#include <cstdint>

#define B_    4
#define KL    128
#define XL    4096
#define DIM   256
#define H_    8
#define HD    32
#define PB    8
#define NDIS  66
#define TDIM  768           // 3*DIM
#define SCALE 0.17677669529663687f
#define NSPLIT 32

// ---------------- scratch (device globals) ----------------
__device__ float    g_QKVx[B_ * XL * TDIM];
__device__ float    g_QKVk[B_ * KL * TDIM];
__device__ unsigned short g_rp[(size_t)B_ * KL * XL];
__device__ uint8_t  g_mb[(size_t)B_ * H_ * KL * (XL / 8)];
__device__ float    g_oriP[NSPLIT * B_ * H_ * KL * PB];
__device__ int      g_mo[B_ * H_ * KL];
__device__ float    g_part[(size_t)B_ * H_ * NSPLIT * KL * 33];
__device__ unsigned g_flags;
__device__ uint32_t g_xhi[B_ * XL * DIM / 2],  g_xlo[B_ * XL * DIM / 2];
__device__ uint32_t g_khi[B_ * KL * DIM / 2],  g_klo[B_ * KL * DIM / 2];
__device__ uint32_t g_wqh[(DIM / 2) * TDIM],   g_wql[(DIM / 2) * TDIM];
__device__ uint32_t g_wph[(DIM / 2) * DIM],    g_wpl[(DIM / 2) * DIM];
__device__ uint32_t g_pXh[B_ * XL * DIM / 2],  g_pXl[B_ * XL * DIM / 2];
__device__ uint32_t g_pKh[B_ * KL * DIM / 2],  g_pKl[B_ * KL * DIM / 2];
__device__ uint32_t g_kqh[B_ * H_ * KL * 16],  g_kql[B_ * H_ * KL * 16];
__device__ uint32_t g_kxh2[(size_t)B_ * H_ * 16 * XL], g_kxl2[(size_t)B_ * H_ * 16 * XL];
__device__ uint32_t g_vxh[(size_t)B_ * H_ * (XL / 2) * 32], g_vxl[(size_t)B_ * H_ * (XL / 2) * 32];
__device__ uint32_t g_qxh[(size_t)B_ * H_ * XL * 16], g_qxl[(size_t)B_ * H_ * XL * 16];

// ---------------- bf16 split helper ----------------
__device__ __forceinline__ uint32_t split_pack(float x0, float x1, uint32_t& lo_pack)
{
    __nv_bfloat16 h0 = __float2bfloat16(x0);
    __nv_bfloat16 h1 = __float2bfloat16(x1);
    float l0 = x0 - __bfloat162float(h0);
    float l1 = x1 - __bfloat162float(h1);
    __nv_bfloat162 hp = __halves2bfloat162(h0, h1);
    __nv_bfloat162 lp = __halves2bfloat162(__float2bfloat16(l0), __float2bfloat16(l1));
    lo_pack = *(uint32_t*)&lp;
    return *(uint32_t*)&hp;
}

// ---------------- mask dtype probe ----------------
__global__ void det_reset() { if (threadIdx.x == 0) g_flags = 0u; }

__global__ void det_scan(const unsigned* __restrict__ w)
{
    int i = blockIdx.x * blockDim.x + threadIdx.x;
    unsigned v = w[i];
    unsigned f = 0;
    if (v == 0x3F800000u) f |= 1u;
    else if (v != 0u && v != 1u) f |= 2u;
    for (int o = 16; o > 0; o >>= 1) f |= __shfl_xor_sync(0xffffffffu, f, o);
    if ((threadIdx.x & 31) == 0 && f) atomicOr(&g_flags, f);
}

// ---------------- rp16 ----------------
__global__ void rp16(const int* __restrict__ rd, const int* __restrict__ polar)
{
    int i = blockIdx.x * blockDim.x + threadIdx.x;
    if (i >= B_ * KL * XL / 2) return;
    int2 r = *(const int2*)&rd[2 * i];
    int2 p = *(const int2*)&polar[2 * i];
    unsigned lo = (unsigned)(r.x | (p.x << 7));
    unsigned hi = (unsigned)(r.y | (p.y << 7));
    ((unsigned*)g_rp)[i] = lo | (hi << 16);
}

// ---------------- maskbit (fast, no smem): grid (XL/64, KL/32, B*H) -------
__global__ __launch_bounds__(256) void maskbit(const void* __restrict__ mask)
{
    unsigned flags = g_flags;
    int mode = (flags & 1u) ? 2 : ((flags & 2u) ? 0 : 1);
    int x0 = blockIdx.x * 64, k0 = blockIdx.y * 32, bh = blockIdx.z;
    int ki = threadIdx.x & 31, jb = threadIdx.x >> 5;   // lane = k -> coalesced loads
    size_t base = ((size_t)bh * XL + x0 + jb * 8) * KL + k0 + ki;
    uint8_t byte = 0;
    if (mode == 1) {
        const int* m = (const int*)mask;
#pragma unroll
        for (int i = 0; i < 8; i++)
            byte |= (uint8_t)((m[base + (size_t)i * KL] != 0) << i);
    } else if (mode == 2) {
        const float* m = (const float*)mask;
#pragma unroll
        for (int i = 0; i < 8; i++)
            byte |= (uint8_t)((m[base + (size_t)i * KL] != 0.f) << i);
    } else {
        const uint8_t* m = (const uint8_t*)mask;
#pragma unroll
        for (int i = 0; i < 8; i++)
            byte |= (uint8_t)((m[base + (size_t)i * KL] != 0) << i);
    }
    g_mb[((size_t)bh * KL + k0 + ki) * (XL / 8) + (x0 >> 3) + jb] = byte;
}

// ---------------- presplit kernels ----------------
__global__ void presplitA(const float* __restrict__ A,
                          uint32_t* __restrict__ hi, uint32_t* __restrict__ lo, int n)
{
    int i = blockIdx.x * blockDim.x + threadIdx.x;
    if (i >= n) return;
    float2 v = *(const float2*)&A[2 * i];
    uint32_t l, h = split_pack(v.x, v.y, l);
    hi[i] = h; lo[i] = l;
}

__global__ void presplitB(const float* __restrict__ Bm,
                          uint32_t* __restrict__ hi, uint32_t* __restrict__ lo, int N, int n)
{
    int i = blockIdx.x * blockDim.x + threadIdx.x;
    if (i >= n) return;
    int p = i / N, c = i - p * N;
    uint32_t l, h = split_pack(Bm[(size_t)(2 * p) * N + c], Bm[(size_t)(2 * p + 1) * N + c], l);
    hi[i] = h; lo[i] = l;
}

// ---------------- prep kernels ----------------
__global__ void prep_kq()
{
    int i = blockIdx.x * blockDim.x + threadIdx.x;
    if (i >= B_ * H_ * KL * 16) return;
    int dp = i & 15;
    int k = (i >> 4) & (KL - 1);
    int bh = i >> 11;
    int b = bh >> 3, h = bh & 7;
    const float* src = &g_QKVk[((size_t)(b * KL + k)) * TDIM + h * HD + 2 * dp];
    uint32_t l, hh = split_pack(src[0], src[1], l);
    g_kqh[i] = hh;
    g_kql[i] = l;
}

__global__ __launch_bounds__(128) void prep_kxv()
{
    __shared__ float kx_sh[64][33];
    __shared__ float v_sh[64][33];
    int tid = threadIdx.x;
    int xt = blockIdx.x, h = blockIdx.y, b = blockIdx.z;
    int bh = b * H_ + h;
    int x0 = xt * 64;

    for (int g = tid; g < 512; g += 128) {
        int row = g >> 3, c4 = g & 7;
        size_t rb = ((size_t)(b * XL + x0 + row)) * TDIM + h * HD + c4 * 4;
        float4 a = *(const float4*)&g_QKVx[rb + DIM];
        float4 v = *(const float4*)&g_QKVx[rb + 2 * DIM];
        kx_sh[row][c4 * 4 + 0] = a.x; kx_sh[row][c4 * 4 + 1] = a.y;
        kx_sh[row][c4 * 4 + 2] = a.z; kx_sh[row][c4 * 4 + 3] = a.w;
        v_sh[row][c4 * 4 + 0] = v.x;  v_sh[row][c4 * 4 + 1] = v.y;
        v_sh[row][c4 * 4 + 2] = v.z;  v_sh[row][c4 * 4 + 3] = v.w;
    }
    __syncthreads();
#pragma unroll
    for (int i = 0; i < 8; i++) {
        int e = tid + 128 * i;
        int dp = e >> 6, xx = e & 63;
        uint32_t l, hh = split_pack(kx_sh[xx][2 * dp], kx_sh[xx][2 * dp + 1], l);
        size_t o = ((size_t)bh * 16 + dp) * XL + x0 + xx;
        g_kxh2[o] = hh;
        g_kxl2[o] = l;
    }
#pragma unroll
    for (int i = 0; i < 8; i++) {
        int e = tid + 128 * i;
        int xp = e >> 5, d = e & 31;
        uint32_t l, hh = split_pack(v_sh[2 * xp][d], v_sh[2 * xp + 1][d], l);
        size_t o = ((size_t)bh * (XL / 2) + (x0 >> 1) + xp) * 32 + d;
        g_vxh[o] = hh;
        g_vxl[o] = l;
    }
}

__global__ void prep_qx()
{
    int i = blockIdx.x * blockDim.x + threadIdx.x;
    if (i >= B_ * H_ * XL * 16) return;
    int dp = i & 15;
    int x = (i >> 4) & (XL - 1);
    int bh = i >> 16;
    int b = bh >> 3, h = bh & 7;
    const float* src = &g_QKVx[((size_t)(b * XL + x)) * TDIM + h * HD + 2 * dp];
    uint32_t l, hh = split_pack(src[0], src[1], l);
    g_qxh[i] = hh;
    g_qxl[i] = l;
}

// ---------------- bf16x3 GEMM ----------------
__device__ __forceinline__ void mma_bf16(float* c, const uint32_t* a, uint32_t b0, uint32_t b1)
{
    asm("mma.sync.aligned.m16n8k16.row.col.f32.bf16.bf16.f32 "
        "{%0,%1,%2,%3}, {%4,%5,%6,%7}, {%8,%9}, {%0,%1,%2,%3};"
        : "+f"(c[0]), "+f"(c[1]), "+f"(c[2]), "+f"(c[3])
        : "r"(a[0]), "r"(a[1]), "r"(a[2]), "r"(a[3]), "r"(b0), "r"(b1));
}

__global__ __launch_bounds__(256, 2) void gemm_pre(
    const uint32_t* __restrict__ Ahi, const uint32_t* __restrict__ Alo,
    const uint32_t* __restrict__ Bhi, const uint32_t* __restrict__ Blo,
    const float* __restrict__ bias, float* __restrict__ C,
    int M, int N, int K)
{
    __shared__ uint32_t AsH[128][20];
    __shared__ uint32_t AsL[128][20];
    __shared__ uint32_t BsH[16][136];
    __shared__ uint32_t BsL[16][136];
    int tid = threadIdx.x;
    int wid = tid >> 5, lane = tid & 31;
    int g = lane >> 2, t = lane & 3;
    int wm = wid & 1, wn = wid >> 1;
    int cCol = blockIdx.x, cRow = blockIdx.y;
    const int KP = K >> 1;

    float acc[4][4][4];
#pragma unroll
    for (int i = 0; i < 4; i++)
#pragma unroll
        for (int j = 0; j < 4; j++)
#pragma unroll
            for (int c = 0; c < 4; c++) acc[i][j][c] = 0.f;

    for (int k0p = 0; k0p < KP; k0p += 16) {
#pragma unroll
        for (int j = 0; j < 4; j++) {
            int f = tid + 256 * j;
            int r = f >> 3, p2 = (f & 7) * 2;
            size_t off = (size_t)(cRow * 128 + r) * KP + k0p + p2;
            uint2 h = *(const uint2*)&Ahi[off];
            uint2 l = *(const uint2*)&Alo[off];
            AsH[r][p2] = h.x; AsH[r][p2 + 1] = h.y;
            AsL[r][p2] = l.x; AsL[r][p2 + 1] = l.y;
        }
#pragma unroll
        for (int j = 0; j < 4; j++) {
            int f = tid + 256 * j;
            int pr = f >> 6, c2 = (f & 63) * 2;
            size_t off = (size_t)(k0p + pr) * N + cCol * 128 + c2;
            uint2 h = *(const uint2*)&Bhi[off];
            uint2 l = *(const uint2*)&Blo[off];
            BsH[pr][c2] = h.x; BsH[pr][c2 + 1] = h.y;
            BsL[pr][c2] = l.x; BsL[pr][c2 + 1] = l.y;
        }
        __syncthreads();

#pragma unroll
        for (int kk = 0; kk < 2; kk++) {
            uint32_t ah[4][4], al[4][4];
#pragma unroll
            for (int mi = 0; mi < 4; mi++) {
                int ar = wm * 64 + mi * 16 + g;
                int pc = kk * 8 + t;
                ah[mi][0] = AsH[ar][pc];         al[mi][0] = AsL[ar][pc];
                ah[mi][1] = AsH[ar + 8][pc];     al[mi][1] = AsL[ar + 8][pc];
                ah[mi][2] = AsH[ar][pc + 4];     al[mi][2] = AsL[ar][pc + 4];
                ah[mi][3] = AsH[ar + 8][pc + 4]; al[mi][3] = AsL[ar + 8][pc + 4];
            }
#pragma unroll
            for (int ni = 0; ni < 4; ni++) {
                int bc = wn * 32 + ni * 8 + g;
                int pr = kk * 8 + t;
                uint32_t bh0 = BsH[pr][bc], bh1 = BsH[pr + 4][bc];
                uint32_t bl0 = BsL[pr][bc], bl1 = BsL[pr + 4][bc];
#pragma unroll
                for (int mi = 0; mi < 4; mi++) {
                    mma_bf16(acc[mi][ni], ah[mi], bh0, bh1);
                    mma_bf16(acc[mi][ni], al[mi], bh0, bh1);
                    mma_bf16(acc[mi][ni], ah[mi], bl0, bl1);
                }
            }
        }
        __syncthreads();
    }

#pragma unroll
    for (int mi = 0; mi < 4; mi++) {
#pragma unroll
        for (int ni = 0; ni < 4; ni++) {
            int r0 = cRow * 128 + wm * 64 + mi * 16 + g;
            int c0 = cCol * 128 + wn * 32 + ni * 8 + 2 * t;
            float b0 = bias ? bias[c0] : 0.f;
            float b1 = bias ? bias[c0 + 1] : 0.f;
            float2 v01 = make_float2(acc[mi][ni][0] + b0, acc[mi][ni][1] + b1);
            float2 v23 = make_float2(acc[mi][ni][2] + b0, acc[mi][ni][3] + b1);
            *(float2*)&C[(size_t)r0 * N + c0] = v01;
            *(float2*)&C[(size_t)(r0 + 8) * N + c0] = v23;
        }
    }
}

// ---------------- K2-MMA: orientation bins via tensor cores ---------------
// grid (NSPLIT, H, B), block 128 (4 warps); warp w owns k rows [32w, 32w+32)
__global__ __launch_bounds__(128) void k2_mma()
{
    __shared__ uint32_t bxh[16][72], bxl[16][72];
    __shared__ uint32_t rp_sh[128 * 33];

    int tid = threadIdx.x;
    int wid = tid >> 5, lane = tid & 31;
    int g = lane >> 2, t = lane & 3;
    int xc = blockIdx.x, h = blockIdx.y, b = blockIdx.z;
    int bh = b * H_ + h;
    int warpk = wid * 32;

    uint32_t aqh[2][2][4], aql[2][2][4];
#pragma unroll
    for (int m = 0; m < 2; m++) {
        int rA = warpk + m * 16 + g;
        int rB = rA + 8;
#pragma unroll
        for (int c = 0; c < 2; c++) {
            size_t baseA = ((size_t)bh * KL + rA) * 16 + c * 8 + t;
            size_t baseB = ((size_t)bh * KL + rB) * 16 + c * 8 + t;
            aqh[m][c][0] = g_kqh[baseA];
            aqh[m][c][1] = g_kqh[baseB];
            aqh[m][c][2] = g_kqh[baseA + 4];
            aqh[m][c][3] = g_kqh[baseB + 4];
            aql[m][c][0] = g_kql[baseA];
            aql[m][c][1] = g_kql[baseB];
            aql[m][c][2] = g_kql[baseA + 4];
            aql[m][c][3] = g_kql[baseB + 4];
        }
    }

    float bins[2][2][8];   // [m][rowA/rowB][bin]
#pragma unroll
    for (int m = 0; m < 2; m++)
#pragma unroll
        for (int r = 0; r < 2; r++)
#pragma unroll
            for (int o = 0; o < 8; o++) bins[m][r][o] = 0.f;

    const unsigned* rp32 = (const unsigned*)g_rp;

    for (int xt = 0; xt < 2; xt++) {
        int x0 = xc * 128 + xt * 64;
        __syncthreads();
#pragma unroll
        for (int i = 0; i < 8; i++) {
            int e = tid + 128 * i;
            int dp = e >> 6, xx = e & 63;
            size_t o = ((size_t)bh * 16 + dp) * XL + x0 + xx;
            bxh[dp][xx] = g_kxh2[o];
            bxl[dp][xx] = g_kxl2[o];
        }
#pragma unroll
        for (int i = 0; i < 32; i++) {
            int e = tid + 128 * i;
            int row = e >> 5, col = e & 31;
            rp_sh[row * 33 + col] = rp32[(size_t)(b * KL + row) * (XL / 2) + (x0 >> 1) + col];
        }
        __syncthreads();

        float sf[2][8][4];
#pragma unroll
        for (int m = 0; m < 2; m++)
#pragma unroll
            for (int j = 0; j < 8; j++) {
                sf[m][j][0] = sf[m][j][1] = sf[m][j][2] = sf[m][j][3] = 0.f;
#pragma unroll
                for (int c = 0; c < 2; c++) {
                    uint32_t b0h = bxh[c * 8 + t][j * 8 + g];
                    uint32_t b1h = bxh[c * 8 + t + 4][j * 8 + g];
                    uint32_t b0l = bxl[c * 8 + t][j * 8 + g];
                    uint32_t b1l = bxl[c * 8 + t + 4][j * 8 + g];
                    mma_bf16(sf[m][j], aqh[m][c], b0h, b1h);
                    mma_bf16(sf[m][j], aql[m][c], b0h, b1h);
                    mma_bf16(sf[m][j], aqh[m][c], b0l, b1l);
                }
            }

#pragma unroll
        for (int m = 0; m < 2; m++) {
            int rA = warpk + m * 16 + g;
            int rB = rA + 8;
#pragma unroll
            for (int j = 0; j < 8; j++) {
                unsigned rpA = rp_sh[rA * 33 + 4 * j + t];
                unsigned rpB = rp_sh[rB * 33 + 4 * j + t];
                float a0 = fabsf(sf[m][j][0] * SCALE);
                float a1 = fabsf(sf[m][j][1] * SCALE);
                float a2 = fabsf(sf[m][j][2] * SCALE);
                float a3 = fabsf(sf[m][j][3] * SCALE);
                int p0 = (rpA >> 7) & 7, p1 = (rpA >> 23) & 7;
                int p2 = (rpB >> 7) & 7, p3 = (rpB >> 23) & 7;
#pragma unroll
                for (int o = 0; o < 8; o++) {
                    bins[m][0][o] += ((p0 == o) ? a0 : 0.f) + ((p1 == o) ? a1 : 0.f);
                    bins[m][1][o] += ((p2 == o) ? a2 : 0.f) + ((p3 == o) ? a3 : 0.f);
                }
            }
        }
    }

    // quad-reduce (t lanes share same k rows) and write
#pragma unroll
    for (int m = 0; m < 2; m++)
#pragma unroll
        for (int r = 0; r < 2; r++)
#pragma unroll
            for (int o = 0; o < 8; o++) {
                float v = bins[m][r][o];
                v += __shfl_xor_sync(0xffffffffu, v, 1);
                v += __shfl_xor_sync(0xffffffffu, v, 2);
                bins[m][r][o] = v;
            }
    if (t == 0) {
#pragma unroll
        for (int m = 0; m < 2; m++)
#pragma unroll
            for (int r = 0; r < 2; r++) {
                int row = warpk + m * 16 + g + r * 8;
                float* op = &g_oriP[((size_t)xc * B_ * H_ * KL + bh * KL + row) * 8];
#pragma unroll
                for (int o = 0; o < 8; o++) op[o] = bins[m][r][o];
            }
    }
}

// ---------------- K2c ----------------
__global__ void k2_argmax()
{
    int idx = blockIdx.x * blockDim.x + threadIdx.x;
    if (idx >= B_ * H_ * KL) return;
    float s[8];
#pragma unroll
    for (int o = 0; o < 8; o++) s[o] = 0.f;
    for (int xc = 0; xc < NSPLIT; xc++) {
        const float* p = &g_oriP[((size_t)xc * B_ * H_ * KL + idx) * 8];
#pragma unroll
        for (int o = 0; o < 8; o++) s[o] += p[o];
    }
    int best = 0;
    float bv = s[0];
#pragma unroll
    for (int p = 1; p < 8; p++)
        if (s[p] > bv) { bv = s[p]; best = p; }
    g_mo[idx] = best;
}

// ---------------- K3-MMA (proven, unchanged) --------------
__global__ __launch_bounds__(128) void k3_mma(
    const float* __restrict__ dis_embed, const float* __restrict__ polar_emb)
{
    __shared__ uint32_t bxh[16][72], bxl[16][72];
    __shared__ uint32_t vsh[32][40], vsl[32][40];
    __shared__ uint32_t rp_sh[128 * 33];
    __shared__ uint64_t mb_sh[128];
    __shared__ float de_sh[NDIS];
    __shared__ float pe_sh[8];

    int tid = threadIdx.x;
    int wid = tid >> 5, lane = tid & 31;
    int g = lane >> 2, t = lane & 3;
    int xc = blockIdx.x, h = blockIdx.y, b = blockIdx.z;
    int bh = b * H_ + h;
    int warpk = wid * 32;

    if (tid < NDIS) de_sh[tid] = dis_embed[tid * H_ + h];
    if (tid < 8) pe_sh[tid] = polar_emb[tid];

    uint32_t aqh[2][2][4], aql[2][2][4];
    int mov[2][2];
#pragma unroll
    for (int m = 0; m < 2; m++) {
        int rA = warpk + m * 16 + g;
        int rB = rA + 8;
#pragma unroll
        for (int c = 0; c < 2; c++) {
            size_t baseA = ((size_t)bh * KL + rA) * 16 + c * 8 + t;
            size_t baseB = ((size_t)bh * KL + rB) * 16 + c * 8 + t;
            aqh[m][c][0] = g_kqh[baseA];
            aqh[m][c][1] = g_kqh[baseB];
            aqh[m][c][2] = g_kqh[baseA + 4];
            aqh[m][c][3] = g_kqh[baseB + 4];
            aql[m][c][0] = g_kql[baseA];
            aql[m][c][1] = g_kql[baseB];
            aql[m][c][2] = g_kql[baseA + 4];
            aql[m][c][3] = g_kql[baseB + 4];
        }
        mov[m][0] = g_mo[bh * KL + rA];
        mov[m][1] = g_mo[bh * KL + rB];
    }

    float accd[2][4][4];
#pragma unroll
    for (int m = 0; m < 2; m++)
#pragma unroll
        for (int n = 0; n < 4; n++)
#pragma unroll
            for (int c = 0; c < 4; c++) accd[m][n][c] = 0.f;
    float lr[2][2] = {{0.f, 0.f}, {0.f, 0.f}};

    const unsigned* rp32 = (const unsigned*)g_rp;

    for (int xt = 0; xt < 2; xt++) {
        int x0 = xc * 128 + xt * 64;
        __syncthreads();
#pragma unroll
        for (int i = 0; i < 8; i++) {
            int e = tid + 128 * i;
            int dp = e >> 6, xx = e & 63;
            size_t o = ((size_t)bh * 16 + dp) * XL + x0 + xx;
            bxh[dp][xx] = g_kxh2[o];
            bxl[dp][xx] = g_kxl2[o];
        }
#pragma unroll
        for (int i = 0; i < 8; i++) {
            int e = tid + 128 * i;
            int xp = e >> 5, d = e & 31;
            size_t o = ((size_t)bh * (XL / 2) + (x0 >> 1) + xp) * 32 + d;
            vsh[xp][d] = g_vxh[o];
            vsl[xp][d] = g_vxl[o];
        }
#pragma unroll
        for (int i = 0; i < 32; i++) {
            int e = tid + 128 * i;
            int row = e >> 5, col = e & 31;
            rp_sh[row * 33 + col] = rp32[(size_t)(b * KL + row) * (XL / 2) + (x0 >> 1) + col];
        }
        mb_sh[tid] = *(const uint64_t*)&g_mb[((size_t)bh * KL + tid) * (XL / 8) + (x0 >> 3)];
        __syncthreads();

        float sf[2][8][4];
#pragma unroll
        for (int m = 0; m < 2; m++)
#pragma unroll
            for (int j = 0; j < 8; j++) {
                sf[m][j][0] = sf[m][j][1] = sf[m][j][2] = sf[m][j][3] = 0.f;
#pragma unroll
                for (int c = 0; c < 2; c++) {
                    uint32_t b0h = bxh[c * 8 + t][j * 8 + g];
                    uint32_t b1h = bxh[c * 8 + t + 4][j * 8 + g];
                    uint32_t b0l = bxl[c * 8 + t][j * 8 + g];
                    uint32_t b1l = bxl[c * 8 + t + 4][j * 8 + g];
                    mma_bf16(sf[m][j], aqh[m][c], b0h, b1h);
                    mma_bf16(sf[m][j], aql[m][c], b0h, b1h);
                    mma_bf16(sf[m][j], aqh[m][c], b0l, b1l);
                }
            }

#pragma unroll
        for (int m = 0; m < 2; m++) {
            int rA = warpk + m * 16 + g;
            int rB = rA + 8;
            uint64_t mA = mb_sh[rA];
            uint64_t mB = mb_sh[rB];
            int moA = mov[m][0], moB = mov[m][1];
#pragma unroll
            for (int cc = 0; cc < 4; cc++) {
                float wv[2][4];
#pragma unroll
                for (int jl = 0; jl < 2; jl++) {
                    int j = 2 * cc + jl;
                    unsigned rpA = rp_sh[rA * 33 + 4 * j + t];
                    unsigned rpB = rp_sh[rB * 33 + 4 * j + t];
                    float s0 = sf[m][j][0] * SCALE;
                    float s1 = sf[m][j][1] * SCALE;
                    float s2 = sf[m][j][2] * SCALE;
                    float s3 = sf[m][j][3] * SCALE;
                    float t0 = s0 + de_sh[rpA & 127] + pe_sh[(((rpA >> 7) & 7) - moA) & 7];
                    float t1 = s1 + de_sh[(rpA >> 16) & 127] + pe_sh[(((rpA >> 23) & 7) - moA) & 7];
                    float t2 = s2 + de_sh[rpB & 127] + pe_sh[(((rpB >> 7) & 7) - moB) & 7];
                    float t3 = s3 + de_sh[(rpB >> 16) & 127] + pe_sh[(((rpB >> 23) & 7) - moB) & 7];
                    int xb = 8 * j + 2 * t;
                    float w0 = ((mA >> xb) & 1) ? 0.f : __expf(t0);
                    float w1 = ((mA >> (xb + 1)) & 1) ? 0.f : __expf(t1);
                    float w2 = ((mB >> xb) & 1) ? 0.f : __expf(t2);
                    float w3 = ((mB >> (xb + 1)) & 1) ? 0.f : __expf(t3);
                    lr[m][0] += w0 + w1;
                    lr[m][1] += w2 + w3;
                    wv[jl][0] = w0; wv[jl][1] = w1; wv[jl][2] = w2; wv[jl][3] = w3;
                }
                uint32_t pah[4], pal[4];
                pah[0] = split_pack(wv[0][0], wv[0][1], pal[0]);
                pah[1] = split_pack(wv[0][2], wv[0][3], pal[1]);
                pah[2] = split_pack(wv[1][0], wv[1][1], pal[2]);
                pah[3] = split_pack(wv[1][2], wv[1][3], pal[3]);
#pragma unroll
                for (int n = 0; n < 4; n++) {
                    uint32_t b0h = vsh[cc * 8 + t][n * 8 + g];
                    uint32_t b1h = vsh[cc * 8 + t + 4][n * 8 + g];
                    uint32_t b0l = vsl[cc * 8 + t][n * 8 + g];
                    uint32_t b1l = vsl[cc * 8 + t + 4][n * 8 + g];
                    mma_bf16(accd[m][n], pah, b0h, b1h);
                    mma_bf16(accd[m][n], pal, b0h, b1h);
                    mma_bf16(accd[m][n], pah, b0l, b1l);
                }
            }
        }
    }

#pragma unroll
    for (int m = 0; m < 2; m++) {
        int rA = warpk + m * 16 + g;
        int rB = rA + 8;
        float lA = lr[m][0];
        lA += __shfl_xor_sync(0xffffffffu, lA, 1);
        lA += __shfl_xor_sync(0xffffffffu, lA, 2);
        float lB = lr[m][1];
        lB += __shfl_xor_sync(0xffffffffu, lB, 1);
        lB += __shfl_xor_sync(0xffffffffu, lB, 2);
        float* ppA = &g_part[(((size_t)bh * NSPLIT + xc) * KL + rA) * 33];
        float* ppB = &g_part[(((size_t)bh * NSPLIT + xc) * KL + rB) * 33];
        if (t == 0) { ppA[0] = lA; ppB[0] = lB; }
#pragma unroll
        for (int n = 0; n < 4; n++) {
            ppA[1 + n * 8 + 2 * t] = accd[m][n][0];
            ppA[2 + n * 8 + 2 * t] = accd[m][n][1];
            ppB[1 + n * 8 + 2 * t] = accd[m][n][2];
            ppB[2 + n * 8 + 2 * t] = accd[m][n][3];
        }
    }
}

// ---------------- K3c ----------------
__global__ void k3_combine()
{
    int idx = blockIdx.x * blockDim.x + threadIdx.x;
    if (idx >= B_ * H_ * KL * 16) return;
    int d2 = idx & 15;
    int k = (idx >> 4) & (KL - 1);
    int bh = idx >> 11;
    int h = bh % H_, b = bh / H_;
    const float* base = &g_part[((size_t)bh * NSPLIT) * KL * 33 + (size_t)k * 33];
    float L = 0.f, A0 = 0.f, A1 = 0.f;
    const size_t SSTR = (size_t)KL * 33;
#pragma unroll 8
    for (int s = 0; s < NSPLIT; s++) {
        L  += base[s * SSTR];
        A0 += base[s * SSTR + 1 + 2 * d2];
        A1 += base[s * SSTR + 2 + 2 * d2];
    }
    float invL = 1.f / L;
    uint32_t lo, hi = split_pack(A0 * invL, A1 * invL, lo);
    size_t o = ((size_t)b * KL + k) * (DIM / 2) + h * (HD / 2) + d2;
    g_pKh[o] = hi;
    g_pKl[o] = lo;
}

// ---------------- K4-MMA (proven, unchanged) ------------
__global__ __launch_bounds__(128) void k4_mma(
    const float* __restrict__ dis_embed, const float* __restrict__ polar_emb)
{
    __shared__ uint32_t kkb_h[16][136], kkb_l[16][136];
    __shared__ uint32_t kvb_h[64][40],  kvb_l[64][40];
    __shared__ uint32_t mb_sh[128][4];
    __shared__ float de_sh[NDIS];
    __shared__ float pe_sh[8];
    __shared__ int   mo_sh[KL];

    int tid = threadIdx.x;
    int wid = tid >> 5, lane = tid & 31;
    int g = lane >> 2, t = lane & 3;
    int xc = blockIdx.x, h = blockIdx.y, b = blockIdx.z;
    int bh = b * H_ + h;
    int warpx = wid * 32;

#pragma unroll
    for (int i = 0; i < 16; i++) {
        int e = tid + 128 * i;
        int k = e >> 4, dp = e & 15;
        float2 v = *(const float2*)&g_QKVk[((size_t)(b * KL + k)) * TDIM + DIM + h * HD + 2 * dp];
        uint32_t l, hh = split_pack(v.x, v.y, l);
        kkb_h[dp][k] = hh;
        kkb_l[dp][k] = l;
    }
#pragma unroll
    for (int i = 0; i < 16; i++) {
        int e = tid + 128 * i;
        int kp = e >> 5, d = e & 31;
        float v0 = g_QKVk[((size_t)(b * KL + 2 * kp)) * TDIM + 2 * DIM + h * HD + d];
        float v1 = g_QKVk[((size_t)(b * KL + 2 * kp + 1)) * TDIM + 2 * DIM + h * HD + d];
        uint32_t l, hh = split_pack(v0, v1, l);
        kvb_h[kp][d] = hh;
        kvb_l[kp][d] = l;
    }
    *(uint4*)&mb_sh[tid][0] =
        *(const uint4*)&g_mb[((size_t)bh * KL + tid) * (XL / 8) + xc * 16];
    if (tid < NDIS) de_sh[tid] = dis_embed[tid * H_ + h];
    if (tid < 8) pe_sh[tid] = polar_emb[tid];
    mo_sh[tid] = g_mo[bh * KL + tid];
    __syncthreads();

    uint32_t aqh[2][2][4], aql[2][2][4];
#pragma unroll
    for (int m = 0; m < 2; m++) {
        int rA = xc * 128 + warpx + m * 16 + g;
        int rB = rA + 8;
#pragma unroll
        for (int c = 0; c < 2; c++) {
            size_t baseA = ((size_t)bh * XL + rA) * 16 + c * 8 + t;
            size_t baseB = ((size_t)bh * XL + rB) * 16 + c * 8 + t;
            aqh[m][c][0] = g_qxh[baseA];
            aqh[m][c][1] = g_qxh[baseB];
            aqh[m][c][2] = g_qxh[baseA + 4];
            aqh[m][c][3] = g_qxh[baseB + 4];
            aql[m][c][0] = g_qxl[baseA];
            aql[m][c][1] = g_qxl[baseB];
            aql[m][c][2] = g_qxl[baseA + 4];
            aql[m][c][3] = g_qxl[baseB + 4];
        }
    }

    float accd[2][4][4];
#pragma unroll
    for (int m = 0; m < 2; m++)
#pragma unroll
        for (int n = 0; n < 4; n++)
#pragma unroll
            for (int c = 0; c < 4; c++) accd[m][n][c] = 0.f;
    float lr[2][2] = {{0.f, 0.f}, {0.f, 0.f}};

    for (int kt = 0; kt < 2; kt++) {
        float sf[2][8][4];
#pragma unroll
        for (int m = 0; m < 2; m++)
#pragma unroll
            for (int j = 0; j < 8; j++) {
                sf[m][j][0] = sf[m][j][1] = sf[m][j][2] = sf[m][j][3] = 0.f;
#pragma unroll
                for (int c = 0; c < 2; c++) {
                    uint32_t b0h = kkb_h[c * 8 + t][kt * 64 + j * 8 + g];
                    uint32_t b1h = kkb_h[c * 8 + t + 4][kt * 64 + j * 8 + g];
                    uint32_t b0l = kkb_l[c * 8 + t][kt * 64 + j * 8 + g];
                    uint32_t b1l = kkb_l[c * 8 + t + 4][kt * 64 + j * 8 + g];
                    mma_bf16(sf[m][j], aqh[m][c], b0h, b1h);
                    mma_bf16(sf[m][j], aql[m][c], b0h, b1h);
                    mma_bf16(sf[m][j], aqh[m][c], b0l, b1l);
                }
            }

#pragma unroll
        for (int m = 0; m < 2; m++) {
            int xbA = warpx + m * 16 + g;
            int xbB = xbA + 8;
            int xA = xc * 128 + xbA;
            int xB = xA + 8;
#pragma unroll
            for (int cc = 0; cc < 4; cc++) {
                float wv[2][4];
#pragma unroll
                for (int jl = 0; jl < 2; jl++) {
                    int j = 2 * cc + jl;
                    int kc0 = kt * 64 + j * 8 + 2 * t;
                    int kc1 = kc0 + 1;
                    unsigned short rp0A = g_rp[(size_t)(b * KL + kc0) * XL + xA];
                    unsigned short rp1A = g_rp[(size_t)(b * KL + kc1) * XL + xA];
                    unsigned short rp0B = g_rp[(size_t)(b * KL + kc0) * XL + xB];
                    unsigned short rp1B = g_rp[(size_t)(b * KL + kc1) * XL + xB];
                    int mo0 = mo_sh[kc0], mo1 = mo_sh[kc1];
                    float t0 = sf[m][j][0] * SCALE + de_sh[rp0A & 127] + pe_sh[(((rp0A >> 7) & 7) - mo0) & 7];
                    float t1 = sf[m][j][1] * SCALE + de_sh[rp1A & 127] + pe_sh[(((rp1A >> 7) & 7) - mo1) & 7];
                    float t2 = sf[m][j][2] * SCALE + de_sh[rp0B & 127] + pe_sh[(((rp0B >> 7) & 7) - mo0) & 7];
                    float t3 = sf[m][j][3] * SCALE + de_sh[rp1B & 127] + pe_sh[(((rp1B >> 7) & 7) - mo1) & 7];
                    float w0 = ((mb_sh[kc0][xbA >> 5] >> (xbA & 31)) & 1u) ? 0.f : __expf(t0);
                    float w1 = ((mb_sh[kc1][xbA >> 5] >> (xbA & 31)) & 1u) ? 0.f : __expf(t1);
                    float w2 = ((mb_sh[kc0][xbB >> 5] >> (xbB & 31)) & 1u) ? 0.f : __expf(t2);
                    float w3 = ((mb_sh[kc1][xbB >> 5] >> (xbB & 31)) & 1u) ? 0.f : __expf(t3);
                    lr[m][0] += w0 + w1;
                    lr[m][1] += w2 + w3;
                    wv[jl][0] = w0; wv[jl][1] = w1; wv[jl][2] = w2; wv[jl][3] = w3;
                }
                uint32_t pah[4], pal[4];
                pah[0] = split_pack(wv[0][0], wv[0][1], pal[0]);
                pah[1] = split_pack(wv[0][2], wv[0][3], pal[1]);
                pah[2] = split_pack(wv[1][0], wv[1][1], pal[2]);
                pah[3] = split_pack(wv[1][2], wv[1][3], pal[3]);
#pragma unroll
                for (int n = 0; n < 4; n++) {
                    uint32_t b0h = kvb_h[kt * 32 + cc * 8 + t][n * 8 + g];
                    uint32_t b1h = kvb_h[kt * 32 + cc * 8 + t + 4][n * 8 + g];
                    uint32_t b0l = kvb_l[kt * 32 + cc * 8 + t][n * 8 + g];
                    uint32_t b1l = kvb_l[kt * 32 + cc * 8 + t + 4][n * 8 + g];
                    mma_bf16(accd[m][n], pah, b0h, b1h);
                    mma_bf16(accd[m][n], pal, b0h, b1h);
                    mma_bf16(accd[m][n], pah, b0l, b1l);
                }
            }
        }
    }

#pragma unroll
    for (int m = 0; m < 2; m++) {
        int xA = xc * 128 + warpx + m * 16 + g;
        int xB = xA + 8;
        float lA = lr[m][0];
        lA += __shfl_xor_sync(0xffffffffu, lA, 1);
        lA += __shfl_xor_sync(0xffffffffu, lA, 2);
        float lB = lr[m][1];
        lB += __shfl_xor_sync(0xffffffffu, lB, 1);
        lB += __shfl_xor_sync(0xffffffffu, lB, 2);
        float invA = 1.f / lA, invB = 1.f / lB;
        size_t obA = ((size_t)(b * XL + xA)) * (DIM / 2) + h * (HD / 2);
        size_t obB = ((size_t)(b * XL + xB)) * (DIM / 2) + h * (HD / 2);
#pragma unroll
        for (int n = 0; n < 4; n++) {
            int dp = n * 4 + t;
            uint32_t loA, hiA = split_pack(accd[m][n][0] * invA, accd[m][n][1] * invA, loA);
            uint32_t loB, hiB = split_pack(accd[m][n][2] * invB, accd[m][n][3] * invB, loB);
            g_pXh[obA + dp] = hiA; g_pXl[obA + dp] = loA;
            g_pXh[obB + dp] = hiB; g_pXl[obB + dp] = loB;
        }
    }
}

// ---------------- host launcher ----------------
extern "C" void kernel_launch(void* const* d_in, const int* in_sizes, int n_in,
                              void* d_out, int out_size)
{
    const float* x     = (const float*)d_in[0];
    const float* kern  = (const float*)d_in[1];
    const int*   rd    = (const int*)d_in[2];
    const int*   polar = (const int*)d_in[3];
    const void*  mask  = d_in[4];
    const float* Wqkv  = (const float*)d_in[5];
    const float* dis   = (const float*)d_in[6];
    const float* pemb  = (const float*)d_in[7];
    const float* Wproj = (const float*)d_in[8];
    const float* bproj = (const float*)d_in[9];
    float* out = (float*)d_out;

    float* pQKVx; cudaGetSymbolAddress((void**)&pQKVx, g_QKVx);
    float* pQKVk; cudaGetSymbolAddress((void**)&pQKVk, g_QKVk);
    uint32_t *pxh, *pxl, *pkh, *pkl, *pwqh, *pwql, *pwph, *pwpl, *pXh, *pXl, *pKh, *pKl;
    cudaGetSymbolAddress((void**)&pxh, g_xhi);  cudaGetSymbolAddress((void**)&pxl, g_xlo);
    cudaGetSymbolAddress((void**)&pkh, g_khi);  cudaGetSymbolAddress((void**)&pkl, g_klo);
    cudaGetSymbolAddress((void**)&pwqh, g_wqh); cudaGetSymbolAddress((void**)&pwql, g_wql);
    cudaGetSymbolAddress((void**)&pwph, g_wph); cudaGetSymbolAddress((void**)&pwpl, g_wpl);
    cudaGetSymbolAddress((void**)&pXh, g_pXh);  cudaGetSymbolAddress((void**)&pXl, g_pXl);
    cudaGetSymbolAddress((void**)&pKh, g_pKh);  cudaGetSymbolAddress((void**)&pKl, g_pKl);

    // mask dtype probe + compact bias/mask tables
    det_reset<<<1, 32>>>();
    det_scan<<<256, 256>>>((const unsigned*)mask);
    rp16<<<(B_ * KL * XL / 2 + 255) / 256, 256>>>(rd, polar);
    maskbit<<<dim3(XL / 64, KL / 32, B_ * H_), 256>>>(mask);

    // pre-split GEMM operands
    presplitA<<<(B_ * XL * DIM / 2 + 255) / 256, 256>>>(x, pxh, pxl, B_ * XL * DIM / 2);
    presplitA<<<(B_ * KL * DIM / 2 + 255) / 256, 256>>>(kern, pkh, pkl, B_ * KL * DIM / 2);
    presplitB<<<((DIM / 2) * TDIM + 255) / 256, 256>>>(Wqkv, pwqh, pwql, TDIM, (DIM / 2) * TDIM);
    presplitB<<<((DIM / 2) * DIM + 255) / 256, 256>>>(Wproj, pwph, pwpl, DIM, (DIM / 2) * DIM);

    // QKV projections
    gemm_pre<<<dim3(TDIM / 128, (B_ * XL) / 128), 256>>>(pxh, pxl, pwqh, pwql, nullptr, pQKVx, B_ * XL, TDIM, DIM);
    gemm_pre<<<dim3(TDIM / 128, (B_ * KL) / 128), 256>>>(pkh, pkl, pwqh, pwql, nullptr, pQKVk, B_ * KL, TDIM, DIM);

    // attention operand prep
    prep_kq<<<(B_ * H_ * KL * 16 + 255) / 256, 256>>>();
    prep_kxv<<<dim3(XL / 64, H_, B_), 128>>>();
    prep_qx<<<(B_ * H_ * XL * 16 + 255) / 256, 256>>>();

    // orientation bins (tensor cores) + argmax
    k2_mma<<<dim3(NSPLIT, H_, B_), 128>>>();
    k2_argmax<<<(B_ * H_ * KL + 255) / 256, 256>>>();

    // kernel->x attention (tensor cores)
    k3_mma<<<dim3(NSPLIT, H_, B_), 128>>>(dis, pemb);
    k3_combine<<<(B_ * H_ * KL * 16 + 255) / 256, 256>>>();

    // x->kernel attention (tensor cores)
    k4_mma<<<dim3(XL / 128, H_, B_), 128>>>(dis, pemb);

    // output projections
    gemm_pre<<<dim3(DIM / 128, (B_ * XL) / 128), 256>>>(pXh, pXl, pwph, pwpl, bproj, out, B_ * XL, DIM, DIM);
    gemm_pre<<<dim3(DIM / 128, (B_ * KL) / 128), 256>>>(pKh, pKl, pwph, pwpl, bproj, out + (size_t)B_ * XL * DIM, B_ * KL, DIM, DIM);
}